// round 14
// baseline (speedup 1.0000x reference)
#include <cuda_runtime.h>
#include <cuda_fp16.h>
#include <math.h>

#define NN 20000
#define NE 320000
#define DD 128
#define DD3 384
#define LNUM 3

// ---------------- scratch (static device globals) ----------------
__device__ __half g_filters[(size_t)NE * DD3];  // CSR-permuted, fp16, streaming
__device__ float g_dir[(size_t)NE * 4];         // CSR-permuted
__device__ int   g_src[NE];                      // CSR-permuted source node j
__device__ int   g_slot[NE];                     // edge id -> CSR slot
__device__ float g_q[(size_t)NN * DD];
__device__ __half g_x[(size_t)NN * DD3];        // fp16 message features
__device__ float g_mu[(size_t)NN * DD3];
__device__ float g_mu2[(size_t)NN * DD3];
__device__ float g_mumix[(size_t)NN * 768];
__device__ float g_ctx[(size_t)NN * 256];
__device__ float g_dot[(size_t)NN * DD];
__device__ float g_xm[(size_t)NN * DD3];
__device__ int g_cnt[NN];
__device__ int g_rowptr[NN + 1];

__device__ __forceinline__ float siluf(float x) { return x / (1.0f + expf(-x)); }
__device__ __forceinline__ float clip5(float x) { return fminf(fmaxf(x, -5.0f), 5.0f); }

__device__ __forceinline__ void mma_f16(float* c, const unsigned* a, const unsigned* b)
{
    asm volatile(
        "mma.sync.aligned.m16n8k16.row.col.f32.f16.f16.f32 "
        "{%0,%1,%2,%3}, {%4,%5,%6,%7}, {%8,%9}, {%0,%1,%2,%3};"
        : "+f"(c[0]), "+f"(c[1]), "+f"(c[2]), "+f"(c[3])
        : "r"(a[0]), "r"(a[1]), "r"(a[2]), "r"(a[3]), "r"(b[0]), "r"(b[1]));
}

#define HS2 140   // half2 stride for A/B tiles
#define C1S 132   // half2 stride for stage-1 result tile

// ---------------- FP16 tensor-core GEMM: C = act(A[M,K] @ B[K,Nc] + bias) ----------------
// BM=128, BN=128, BK=16. 256 threads = 8 warps in 2(M)x4(N); warp tile 64x32.
template<int ACT, bool OUTH>
__global__ __launch_bounds__(256) void tgemm(const float* __restrict__ A,
                                             const float* __restrict__ B,
                                             const float* __restrict__ bias,
                                             float* __restrict__ C,
                                             int M, int K, int Nc)
{
    __shared__ __half2 As2[2][8][HS2];
    __shared__ __half2 Bs2[2][8][HS2];
    int tid = threadIdx.x;
    int wid = tid >> 5, lane = tid & 31;
    int g = lane >> 2, tg = lane & 3;
    int wm = wid & 1, wn = wid >> 1;
    int row0 = blockIdx.y * 128, col0 = blockIdx.x * 128;

    int arow = tid >> 1, ak2 = (tid & 1) * 4;
    int bk2 = tid >> 5, bcol = (tid & 31) * 4;
    bool aval = (row0 + arow) < M;
    const float* Aptr = A + (size_t)(row0 + arow) * K + ak2 * 2;
    const float* Bp0 = B + (size_t)(2 * bk2) * Nc + col0 + bcol;
    const float* Bp1 = Bp0 + Nc;

    float acc[4][4][4];
#pragma unroll
    for (int mt = 0; mt < 4; mt++)
#pragma unroll
        for (int nt = 0; nt < 4; nt++)
#pragma unroll
            for (int r = 0; r < 4; r++) acc[mt][nt][r] = 0.0f;

    {
        float4 a0 = make_float4(0.f, 0.f, 0.f, 0.f), a1 = a0;
        if (aval) { a0 = *(const float4*)(Aptr); a1 = *(const float4*)(Aptr + 4); }
        As2[0][ak2 + 0][arow] = __floats2half2_rn(a0.x, a0.y);
        As2[0][ak2 + 1][arow] = __floats2half2_rn(a0.z, a0.w);
        As2[0][ak2 + 2][arow] = __floats2half2_rn(a1.x, a1.y);
        As2[0][ak2 + 3][arow] = __floats2half2_rn(a1.z, a1.w);
        float4 b0 = *(const float4*)(Bp0);
        float4 b1 = *(const float4*)(Bp1);
        Bs2[0][bk2][bcol + 0] = __floats2half2_rn(b0.x, b1.x);
        Bs2[0][bk2][bcol + 1] = __floats2half2_rn(b0.y, b1.y);
        Bs2[0][bk2][bcol + 2] = __floats2half2_rn(b0.z, b1.z);
        Bs2[0][bk2][bcol + 3] = __floats2half2_rn(b0.w, b1.w);
    }
    __syncthreads();

    int ntl = K >> 4;
    for (int t = 0; t < ntl; t++) {
        int cur = t & 1, nxt = cur ^ 1;
        float4 na0, na1, nb0, nb1;
        if (t + 1 < ntl) {
            if (aval) {
                na0 = *(const float4*)(Aptr + (t + 1) * 16);
                na1 = *(const float4*)(Aptr + (t + 1) * 16 + 4);
            } else { na0 = make_float4(0.f,0.f,0.f,0.f); na1 = na0; }
            nb0 = *(const float4*)(Bp0 + (size_t)(t + 1) * 16 * Nc);
            nb1 = *(const float4*)(Bp1 + (size_t)(t + 1) * 16 * Nc);
        }
        unsigned ar[4][4], br[4][2];
#pragma unroll
        for (int mt = 0; mt < 4; mt++) {
            int r = wm * 64 + mt * 16 + g;
            ar[mt][0] = *(const unsigned*)&As2[cur][tg][r];
            ar[mt][1] = *(const unsigned*)&As2[cur][tg][r + 8];
            ar[mt][2] = *(const unsigned*)&As2[cur][tg + 4][r];
            ar[mt][3] = *(const unsigned*)&As2[cur][tg + 4][r + 8];
        }
#pragma unroll
        for (int nt = 0; nt < 4; nt++) {
            int n0 = wn * 32 + nt * 8 + g;
            br[nt][0] = *(const unsigned*)&Bs2[cur][tg][n0];
            br[nt][1] = *(const unsigned*)&Bs2[cur][tg + 4][n0];
        }
#pragma unroll
        for (int mt = 0; mt < 4; mt++)
#pragma unroll
            for (int nt = 0; nt < 4; nt++)
                mma_f16(acc[mt][nt], ar[mt], br[nt]);

        if (t + 1 < ntl) {
            As2[nxt][ak2 + 0][arow] = __floats2half2_rn(na0.x, na0.y);
            As2[nxt][ak2 + 1][arow] = __floats2half2_rn(na0.z, na0.w);
            As2[nxt][ak2 + 2][arow] = __floats2half2_rn(na1.x, na1.y);
            As2[nxt][ak2 + 3][arow] = __floats2half2_rn(na1.z, na1.w);
            Bs2[nxt][bk2][bcol + 0] = __floats2half2_rn(nb0.x, nb1.x);
            Bs2[nxt][bk2][bcol + 1] = __floats2half2_rn(nb0.y, nb1.y);
            Bs2[nxt][bk2][bcol + 2] = __floats2half2_rn(nb0.z, nb1.z);
            Bs2[nxt][bk2][bcol + 3] = __floats2half2_rn(nb0.w, nb1.w);
        }
        __syncthreads();
    }

#pragma unroll
    for (int mt = 0; mt < 4; mt++) {
#pragma unroll
        for (int nt = 0; nt < 4; nt++) {
            int col = col0 + wn * 32 + nt * 8 + 2 * tg;
            float bb0 = 0.f, bb1 = 0.f;
            if (bias) { bb0 = bias[col]; bb1 = bias[col + 1]; }
#pragma unroll
            for (int half = 0; half < 2; half++) {
                int row = row0 + wm * 64 + mt * 16 + g + half * 8;
                if (row >= M) continue;
                float v0 = acc[mt][nt][half * 2 + 0] + bb0;
                float v1 = acc[mt][nt][half * 2 + 1] + bb1;
                if (ACT == 1) { v0 = siluf(v0); v1 = siluf(v1); }
                if (OUTH) {
                    __half2* o = (__half2*)((__half*)C + (size_t)row * Nc + col);
                    *o = __floats2half2_rn(v0, v1);
                } else {
                    *(float2*)(C + (size_t)row * Nc + col) = make_float2(v0, v1);
                }
            }
        }
    }
}

// ---------------- Fused 2-layer MLP: C[:,cb] = silu(A@W1+b1) @ W2[:,cb] + b2[:,cb] ----------------
// Static smem 42.75 KB: Bs2 persistent; C1s ALIASES As2 (stage 2 never reads As2;
// the final __syncthreads of stage 1's main loop orders all As2 reads before the overwrite).
// grid = (Nc2/128, ceil(M/128)), 256 threads. K1 % 16 == 0, Nc1 = 128, K2 = 128.
template<bool OUTH>
__global__ __launch_bounds__(256) void tmlp(const float* __restrict__ A,
                                            const float* __restrict__ W1,
                                            const float* __restrict__ b1,
                                            const float* __restrict__ W2,
                                            const float* __restrict__ b2,
                                            float* __restrict__ C,
                                            int M, int K1, int Nc2)
{
    __shared__ __half2 sBs[2 * 8 * HS2];      // B tiles (both stages)
    __shared__ __half2 sU[64 * C1S];          // union: As2 (2*8*HS2=2240 <= 8448) then C1s
    __half2* As2 = sU;
    __half2* Bs2 = sBs;
    __half2* C1s = sU;
#define ASX(b,k,m) As2[((b) * 8 + (k)) * HS2 + (m)]
#define BSX(b,k,m) Bs2[((b) * 8 + (k)) * HS2 + (m)]

    int tid = threadIdx.x;
    int wid = tid >> 5, lane = tid & 31;
    int g = lane >> 2, tg = lane & 3;
    int wm = wid & 1, wn = wid >> 1;
    int row0 = blockIdx.y * 128, col0 = blockIdx.x * 128;

    int arow = tid >> 1, ak2 = (tid & 1) * 4;
    int bk2 = tid >> 5, bcol = (tid & 31) * 4;
    bool aval = (row0 + arow) < M;
    const float* Aptr = A + (size_t)(row0 + arow) * K1 + ak2 * 2;
    const float* Bp0 = W1 + (size_t)(2 * bk2) * 128 + bcol;   // stage-1 B, Nc1=128
    const float* Bp1 = Bp0 + 128;

    float acc[4][4][4];
#pragma unroll
    for (int mt = 0; mt < 4; mt++)
#pragma unroll
        for (int nt = 0; nt < 4; nt++)
#pragma unroll
            for (int r = 0; r < 4; r++) acc[mt][nt][r] = 0.0f;

    // -------- stage 1: silu(A @ W1 + b1) --------
    {
        float4 a0 = make_float4(0.f, 0.f, 0.f, 0.f), a1 = a0;
        if (aval) { a0 = *(const float4*)(Aptr); a1 = *(const float4*)(Aptr + 4); }
        ASX(0, ak2 + 0, arow) = __floats2half2_rn(a0.x, a0.y);
        ASX(0, ak2 + 1, arow) = __floats2half2_rn(a0.z, a0.w);
        ASX(0, ak2 + 2, arow) = __floats2half2_rn(a1.x, a1.y);
        ASX(0, ak2 + 3, arow) = __floats2half2_rn(a1.z, a1.w);
        float4 b0 = *(const float4*)(Bp0);
        float4 b1v = *(const float4*)(Bp1);
        BSX(0, bk2, bcol + 0) = __floats2half2_rn(b0.x, b1v.x);
        BSX(0, bk2, bcol + 1) = __floats2half2_rn(b0.y, b1v.y);
        BSX(0, bk2, bcol + 2) = __floats2half2_rn(b0.z, b1v.z);
        BSX(0, bk2, bcol + 3) = __floats2half2_rn(b0.w, b1v.w);
    }
    __syncthreads();

    int ntl1 = K1 >> 4;
    for (int t = 0; t < ntl1; t++) {
        int cur = t & 1, nxt = cur ^ 1;
        float4 na0, na1, nb0, nb1;
        if (t + 1 < ntl1) {
            if (aval) {
                na0 = *(const float4*)(Aptr + (t + 1) * 16);
                na1 = *(const float4*)(Aptr + (t + 1) * 16 + 4);
            } else { na0 = make_float4(0.f,0.f,0.f,0.f); na1 = na0; }
            nb0 = *(const float4*)(Bp0 + (size_t)(t + 1) * 16 * 128);
            nb1 = *(const float4*)(Bp1 + (size_t)(t + 1) * 16 * 128);
        }
        unsigned ar[4][4], br[4][2];
#pragma unroll
        for (int mt = 0; mt < 4; mt++) {
            int r = wm * 64 + mt * 16 + g;
            ar[mt][0] = *(const unsigned*)&ASX(cur, tg, r);
            ar[mt][1] = *(const unsigned*)&ASX(cur, tg, r + 8);
            ar[mt][2] = *(const unsigned*)&ASX(cur, tg + 4, r);
            ar[mt][3] = *(const unsigned*)&ASX(cur, tg + 4, r + 8);
        }
#pragma unroll
        for (int nt = 0; nt < 4; nt++) {
            int n0 = wn * 32 + nt * 8 + g;
            br[nt][0] = *(const unsigned*)&BSX(cur, tg, n0);
            br[nt][1] = *(const unsigned*)&BSX(cur, tg + 4, n0);
        }
#pragma unroll
        for (int mt = 0; mt < 4; mt++)
#pragma unroll
            for (int nt = 0; nt < 4; nt++)
                mma_f16(acc[mt][nt], ar[mt], br[nt]);

        if (t + 1 < ntl1) {
            ASX(nxt, ak2 + 0, arow) = __floats2half2_rn(na0.x, na0.y);
            ASX(nxt, ak2 + 1, arow) = __floats2half2_rn(na0.z, na0.w);
            ASX(nxt, ak2 + 2, arow) = __floats2half2_rn(na1.x, na1.y);
            ASX(nxt, ak2 + 3, arow) = __floats2half2_rn(na1.z, na1.w);
            BSX(nxt, bk2, bcol + 0) = __floats2half2_rn(nb0.x, nb1.x);
            BSX(nxt, bk2, bcol + 1) = __floats2half2_rn(nb0.y, nb1.y);
            BSX(nxt, bk2, bcol + 2) = __floats2half2_rn(nb0.z, nb1.z);
            BSX(nxt, bk2, bcol + 3) = __floats2half2_rn(nb0.w, nb1.w);
        }
        __syncthreads();
    }

    // stage-1 epilogue: silu + bias -> C1s (aliases As2; all As2 reads complete).
    // Also prologue-load stage-2 B tile 0.
    const float* Bq0 = W2 + (size_t)(2 * bk2) * Nc2 + col0 + bcol;
    const float* Bq1 = Bq0 + Nc2;
#pragma unroll
    for (int mt = 0; mt < 4; mt++) {
#pragma unroll
        for (int nt = 0; nt < 4; nt++) {
            int col = wn * 32 + nt * 8 + 2 * tg;
            int k2c = col >> 1;
            float bb0 = b1[col], bb1 = b1[col + 1];
#pragma unroll
            for (int half = 0; half < 2; half++) {
                int row = wm * 64 + mt * 16 + g + half * 8;
                float v0 = siluf(acc[mt][nt][half * 2 + 0] + bb0);
                float v1 = siluf(acc[mt][nt][half * 2 + 1] + bb1);
                C1s[k2c * C1S + row] = __floats2half2_rn(v0, v1);
            }
        }
    }
    {
        float4 b0 = *(const float4*)(Bq0);
        float4 b1v = *(const float4*)(Bq1);
        BSX(0, bk2, bcol + 0) = __floats2half2_rn(b0.x, b1v.x);
        BSX(0, bk2, bcol + 1) = __floats2half2_rn(b0.y, b1v.y);
        BSX(0, bk2, bcol + 2) = __floats2half2_rn(b0.z, b1v.z);
        BSX(0, bk2, bcol + 3) = __floats2half2_rn(b0.w, b1v.w);
    }
    __syncthreads();

    // -------- stage 2: C1s @ W2 + b2 (K2 = 128) --------
#pragma unroll
    for (int mt = 0; mt < 4; mt++)
#pragma unroll
        for (int nt = 0; nt < 4; nt++)
#pragma unroll
            for (int r = 0; r < 4; r++) acc[mt][nt][r] = 0.0f;

    for (int t = 0; t < 8; t++) {
        int cur = t & 1, nxt = cur ^ 1;
        float4 nb0, nb1;
        if (t + 1 < 8) {
            nb0 = *(const float4*)(Bq0 + (size_t)(t + 1) * 16 * Nc2);
            nb1 = *(const float4*)(Bq1 + (size_t)(t + 1) * 16 * Nc2);
        }
        int kc2 = t * 8;
        unsigned ar[4][4], br[4][2];
#pragma unroll
        for (int mt = 0; mt < 4; mt++) {
            int r = wm * 64 + mt * 16 + g;
            ar[mt][0] = *(const unsigned*)&C1s[(kc2 + tg) * C1S + r];
            ar[mt][1] = *(const unsigned*)&C1s[(kc2 + tg) * C1S + r + 8];
            ar[mt][2] = *(const unsigned*)&C1s[(kc2 + tg + 4) * C1S + r];
            ar[mt][3] = *(const unsigned*)&C1s[(kc2 + tg + 4) * C1S + r + 8];
        }
#pragma unroll
        for (int nt = 0; nt < 4; nt++) {
            int n0 = wn * 32 + nt * 8 + g;
            br[nt][0] = *(const unsigned*)&BSX(cur, tg, n0);
            br[nt][1] = *(const unsigned*)&BSX(cur, tg + 4, n0);
        }
#pragma unroll
        for (int mt = 0; mt < 4; mt++)
#pragma unroll
            for (int nt = 0; nt < 4; nt++)
                mma_f16(acc[mt][nt], ar[mt], br[nt]);

        if (t + 1 < 8) {
            BSX(nxt, bk2, bcol + 0) = __floats2half2_rn(nb0.x, nb1.x);
            BSX(nxt, bk2, bcol + 1) = __floats2half2_rn(nb0.y, nb1.y);
            BSX(nxt, bk2, bcol + 2) = __floats2half2_rn(nb0.z, nb1.z);
            BSX(nxt, bk2, bcol + 3) = __floats2half2_rn(nb0.w, nb1.w);
        }
        __syncthreads();
    }

#pragma unroll
    for (int mt = 0; mt < 4; mt++) {
#pragma unroll
        for (int nt = 0; nt < 4; nt++) {
            int col = col0 + wn * 32 + nt * 8 + 2 * tg;
            float bb0 = b2[col], bb1 = b2[col + 1];
#pragma unroll
            for (int half = 0; half < 2; half++) {
                int row = row0 + wm * 64 + mt * 16 + g + half * 8;
                if (row >= M) continue;
                float v0 = acc[mt][nt][half * 2 + 0] + bb0;
                float v1 = acc[mt][nt][half * 2 + 1] + bb1;
                if (OUTH) {
                    __half2* o = (__half2*)((__half*)C + (size_t)row * Nc2 + col);
                    *o = __floats2half2_rn(v0, v1);
                } else {
                    *(float2*)(C + (size_t)row * Nc2 + col) = make_float2(v0, v1);
                }
            }
        }
    }
#undef ASX
#undef BSX
}

// ---------------- CSR build ----------------
__global__ void init_bufs()
{
    int idx = blockIdx.x * blockDim.x + threadIdx.x;
    if (idx < NN) g_cnt[idx] = 0;
}

__global__ void csr_count(const int* __restrict__ ei)
{
    int e = blockIdx.x * blockDim.x + threadIdx.x;
    if (e < NE) atomicAdd(&g_cnt[ei[e]], 1);
}

__global__ __launch_bounds__(1024) void csr_scan()
{
    __shared__ int part[1024];
    int t = threadIdx.x;
    const int CH = (NN + 1023) / 1024;
    int base = t * CH;
    int s = 0;
    for (int k = 0; k < CH; k++) {
        int n = base + k;
        if (n < NN) s += g_cnt[n];
    }
    part[t] = s;
    __syncthreads();
    for (int off = 1; off < 1024; off <<= 1) {
        int v = (t >= off) ? part[t - off] : 0;
        __syncthreads();
        part[t] += v;
        __syncthreads();
    }
    int run = (t == 0) ? 0 : part[t - 1];
    for (int k = 0; k < CH; k++) {
        int n = base + k;
        if (n < NN) {
            g_rowptr[n] = run;
            run += g_cnt[n];
            g_cnt[n] = 0;
        }
    }
    if (t == 1023) g_rowptr[NN] = run;
}

__global__ void csr_fill(const int* __restrict__ ei)
{
    int e = blockIdx.x * blockDim.x + threadIdx.x;
    if (e < NE) {
        int i = ei[e];
        int pos = atomicAdd(&g_cnt[i], 1);
        int slot = g_rowptr[i] + pos;
        g_slot[e] = slot;
        g_src[slot] = ei[NE + e];
    }
}

// ---------------- per-edge geometry + RBF filters (fp16, streaming stores) ----------------
__global__ __launch_bounds__(256) void edge_pre(const float* __restrict__ pos,
                                                const int* __restrict__ ei,
                                                const float* __restrict__ fw,
                                                const float* __restrict__ fb)
{
    int e = blockIdx.x * 8 + (threadIdx.x >> 5);
    if (e >= NE) return;
    int lane = threadIdx.x & 31;
    int i = ei[e], j = ei[NE + e];
    int slot = g_slot[e];
    float rx = pos[j * 3 + 0] - pos[i * 3 + 0];
    float ry = pos[j * 3 + 1] - pos[i * 3 + 1];
    float rz = pos[j * 3 + 2] - pos[i * 3 + 2];
    float d = sqrtf(rx * rx + ry * ry + rz * rz);
    d = fmaxf(d, 1e-8f);
    float dv = (lane == 0) ? rx : ((lane == 1) ? ry : rz);
    if (lane < 3) g_dir[(size_t)slot * 4 + lane] = dv / d;
    if (lane == 3) g_dir[(size_t)slot * 4 + 3] = 0.f;

    const float spacing = 5.0f / 63.0f;
    const float coeff = -0.5f / (spacing * spacing);
    float xc = fminf(d * 0.2f, 1.0f);
    float fcut = (xc < 1.0f) ? 0.5f * (cospif(xc) + 1.0f) : 0.0f;

    float4 acc0 = make_float4(0.f, 0.f, 0.f, 0.f), acc1 = acc0, acc2 = acc0;
    if (fcut > 0.0f) {
        int k0 = (int)rintf(d / spacing);
        int lo = max(0, k0 - 8), hi = min(63, k0 + 8);
        const float4* fw4 = (const float4*)fw;
        for (int k = lo; k <= hi; k++) {
            float t = d - (float)k * spacing;
            float p = expf(coeff * t * t);
            float4 w0 = fw4[k * 96 + lane];
            float4 w1 = fw4[k * 96 + lane + 32];
            float4 w2 = fw4[k * 96 + lane + 64];
            acc0.x += p * w0.x; acc0.y += p * w0.y; acc0.z += p * w0.z; acc0.w += p * w0.w;
            acc1.x += p * w1.x; acc1.y += p * w1.y; acc1.z += p * w1.z; acc1.w += p * w1.w;
            acc2.x += p * w2.x; acc2.y += p * w2.y; acc2.z += p * w2.z; acc2.w += p * w2.w;
        }
    }
    const float4* fb4 = (const float4*)fb;
    __half2* outh = (__half2*)(g_filters + (size_t)slot * DD3);
#pragma unroll
    for (int grp = 0; grp < 3; grp++) {
        float4 a = (grp == 0) ? acc0 : ((grp == 1) ? acc1 : acc2);
        float4 b = fb4[lane + 32 * grp];
        float v0 = clip5((a.x + b.x) * fcut);
        float v1 = clip5((a.y + b.y) * fcut);
        float v2 = clip5((a.z + b.z) * fcut);
        float v3 = clip5((a.w + b.w) * fcut);
        int base2 = (grp * 128 + lane * 4) >> 1;
        __stcs(outh + base2,     __floats2half2_rn(v0, v1));
        __stcs(outh + base2 + 1, __floats2half2_rn(v2, v3));
    }
}

// ---------------- CSR gather of edge messages (half2-vectorized) ----------------
template<bool MUZERO>
__global__ __launch_bounds__(128) void gather_msg(const float* __restrict__ mu_in,
                                                  float* __restrict__ mu_out)
{
    int n = blockIdx.x * 2 + (threadIdx.x >> 6);
    int c2 = threadIdx.x & 63;
    int s = g_rowptr[n], t = g_rowptr[n + 1];
    float2 aq = make_float2(0.f, 0.f);
    float2 m0 = aq, m1 = aq, m2 = aq;
    for (int k = s; k < t; k++) {
        int j = __ldg(&g_src[k]);
        const __half2* f  = (const __half2*)(g_filters + (size_t)k * DD3);
        const __half2* xj = (const __half2*)(g_x + (size_t)j * DD3);
        float2 fq = __half22float2(__ldcs(f + c2));
        float2 fR = __half22float2(__ldcs(f + 64 + c2));
        float2 fm = __half22float2(__ldcs(f + 128 + c2));
        float2 xq = __half22float2(xj[c2]);
        float2 xR = __half22float2(xj[64 + c2]);
        float2 xm = __half22float2(xj[128 + c2]);
        float4 dv = __ldcs((const float4*)(g_dir + (size_t)k * 4));
        float2 dmuR = make_float2(xR.x * fR.x, xR.y * fR.y);
        aq.x += xq.x * fq.x;
        aq.y += xq.y * fq.y;
        if (MUZERO) {
            m0.x += dmuR.x * dv.x; m0.y += dmuR.y * dv.x;
            m1.x += dmuR.x * dv.y; m1.y += dmuR.y * dv.y;
            m2.x += dmuR.x * dv.z; m2.y += dmuR.y * dv.z;
        } else {
            float2 dmm = make_float2(xm.x * fm.x, xm.y * fm.y);
            const float2* muj = (const float2*)(mu_in + (size_t)j * DD3);
            float2 u0 = muj[c2], u1 = muj[64 + c2], u2 = muj[128 + c2];
            m0.x += dmuR.x * dv.x + dmm.x * u0.x; m0.y += dmuR.y * dv.x + dmm.y * u0.y;
            m1.x += dmuR.x * dv.y + dmm.x * u1.x; m1.y += dmuR.y * dv.y + dmm.y * u1.y;
            m2.x += dmuR.x * dv.z + dmm.x * u2.x; m2.y += dmuR.y * dv.z + dmm.y * u2.y;
        }
    }
    float2* qp = (float2*)(g_q + (size_t)n * DD);
    float2 qv = qp[c2];
    qv.x += aq.x; qv.y += aq.y;
    qp[c2] = qv;
    float2* muo = (float2*)(mu_out + (size_t)n * DD3);
    if (MUZERO) {
        muo[c2]       = m0;
        muo[64 + c2]  = m1;
        muo[128 + c2] = m2;
    } else {
        const float2* mui = (const float2*)(mu_in + (size_t)n * DD3);
        float2 u0 = mui[c2], u1 = mui[64 + c2], u2 = mui[128 + c2];
        u0.x += m0.x; u0.y += m0.y;
        u1.x += m1.x; u1.y += m1.y;
        u2.x += m2.x; u2.y += m2.y;
        muo[c2]       = u0;
        muo[64 + c2]  = u1;
        muo[128 + c2] = u2;
    }
}

// ---------------- mu_Vn / dot(mu_V,mu_W) / ctx ----------------
__global__ __launch_bounds__(128) void reduce_mix()
{
    int n = blockIdx.x, c = threadIdx.x;
    size_t base = (size_t)n * 768;
    float v0 = g_mumix[base + c],        w0 = g_mumix[base + 128 + c];
    float v1 = g_mumix[base + 256 + c],  w1 = g_mumix[base + 384 + c];
    float v2 = g_mumix[base + 512 + c],  w2 = g_mumix[base + 640 + c];
    float vn = sqrtf(v0 * v0 + v1 * v1 + v2 * v2 + 1e-8f);
    g_ctx[(size_t)n * 256 + c]       = g_q[(size_t)n * DD + c];
    g_ctx[(size_t)n * 256 + 128 + c] = vn;
    g_dot[(size_t)n * DD + c] = v0 * w0 + v1 * w1 + v2 * w2;
}

// ---------------- q,mu self-update ----------------
__global__ __launch_bounds__(128) void update_node(float* __restrict__ mu)
{
    int n = blockIdx.x, c = threadIdx.x;
    size_t xb = (size_t)n * DD3;
    float dq_i  = g_xm[xb + c];
    float dmu_i = g_xm[xb + DD + c];
    float dqmu  = g_xm[xb + 2 * DD + c];
    g_q[(size_t)n * DD + c] += dq_i + dqmu * g_dot[(size_t)n * DD + c];
    size_t mb = (size_t)n * 768;
#pragma unroll
    for (int a = 0; a < 3; a++)
        mu[(size_t)n * DD3 + a * DD + c] += dmu_i * g_mumix[mb + a * 256 + 128 + c];
}

// ---------------- final layernorm -> tanh ----------------
__global__ __launch_bounds__(128) void layernorm_out(const float* __restrict__ lng,
                                                     const float* __restrict__ lnb,
                                                     float* __restrict__ out)
{
    int n = blockIdx.x, c = threadIdx.x;
    float v = clip5(g_q[(size_t)n * DD + c]);
    float s = v, s2 = v * v;
#pragma unroll
    for (int o = 16; o; o >>= 1) {
        s  += __shfl_xor_sync(0xffffffffu, s, o);
        s2 += __shfl_xor_sync(0xffffffffu, s2, o);
    }
    __shared__ float sh[4], sh2[4];
    int w = c >> 5, l = c & 31;
    if (l == 0) { sh[w] = s; sh2[w] = s2; }
    __syncthreads();
    float sumv  = sh[0] + sh[1] + sh[2] + sh[3];
    float sumsq = sh2[0] + sh2[1] + sh2[2] + sh2[3];
    float mean = sumv * (1.0f / 128.0f);
    float var  = sumsq * (1.0f / 128.0f) - mean * mean;
    float y = (v - mean) * rsqrtf(var + 1e-5f) * lng[c] + lnb[c];
    out[(size_t)n * DD + c] = tanhf(y);
}

// ---------------- final mu_node gather + pos_attr (fused) ----------------
__global__ __launch_bounds__(128) void pos_gather(const float* __restrict__ mu,
                                                  const float* __restrict__ mpw,
                                                  float* __restrict__ out)
{
    int n = blockIdx.x, c = threadIdx.x;
    int s = g_rowptr[n], t = g_rowptr[n + 1];
    float s0 = 0.f, s1 = 0.f, s2v = 0.f;
    for (int k = s; k < t; k++) {
        int j = __ldg(&g_src[k]);
        const float* muj = mu + (size_t)j * DD3;
        s0  += muj[c];
        s1  += muj[DD + c];
        s2v += muj[2 * DD + c];
    }
    float w = mpw[c];
    s0  = clip5(s0) * w;
    s1  = clip5(s1) * w;
    s2v = clip5(s2v) * w;
#pragma unroll
    for (int o = 16; o; o >>= 1) {
        s0  += __shfl_xor_sync(0xffffffffu, s0, o);
        s1  += __shfl_xor_sync(0xffffffffu, s1, o);
        s2v += __shfl_xor_sync(0xffffffffu, s2v, o);
    }
    __shared__ float sh[4][3];
    int wd = c >> 5, l = c & 31;
    if (l == 0) { sh[wd][0] = s0; sh[wd][1] = s1; sh[wd][2] = s2v; }
    __syncthreads();
    if (c < 3) {
        float v = sh[0][c] + sh[1][c] + sh[2][c] + sh[3][c];
        out[(size_t)n * 3 + c] = clip5(v);
    }
}

// ---------------- launch ----------------
extern "C" void kernel_launch(void* const* d_in, const int* in_sizes, int n_in,
                              void* d_out, int out_size)
{
    const float* z      = (const float*)d_in[0];
    const float* pos    = (const float*)d_in[1];
    const int*   ei     = (const int*)  d_in[2];
    const float* in_w   = (const float*)d_in[3];
    const float* in_b   = (const float*)d_in[4];
    const float* filt_w = (const float*)d_in[5];
    const float* filt_b = (const float*)d_in[6];
    const float* iw1    = (const float*)d_in[7];
    const float* ib1    = (const float*)d_in[8];
    const float* iw2    = (const float*)d_in[9];
    const float* ib2    = (const float*)d_in[10];
    const float* mmw    = (const float*)d_in[11];
    const float* mw1    = (const float*)d_in[12];
    const float* mb1    = (const float*)d_in[13];
    const float* mw2    = (const float*)d_in[14];
    const float* mb2    = (const float*)d_in[15];
    const float* mpw    = (const float*)d_in[16];
    const float* lng    = (const float*)d_in[17];
    const float* lnb    = (const float*)d_in[18];
    float* out = (float*)d_out;

    float *p_q, *p_mu, *p_mu2, *p_mumix, *p_ctx, *p_xm;
    __half* p_x;
    cudaGetSymbolAddress((void**)&p_q,     g_q);
    cudaGetSymbolAddress((void**)&p_x,     g_x);
    cudaGetSymbolAddress((void**)&p_mu,    g_mu);
    cudaGetSymbolAddress((void**)&p_mu2,   g_mu2);
    cudaGetSymbolAddress((void**)&p_mumix, g_mumix);
    cudaGetSymbolAddress((void**)&p_ctx,   g_ctx);
    cudaGetSymbolAddress((void**)&p_xm,    g_xm);

    int gy_n  = (NN + 127) / 128;        // 157
    int gy_3n = (3 * NN + 127) / 128;    // 469

    init_bufs<<<(NN + 255) / 256, 256>>>();
    csr_count<<<(NE + 255) / 256, 256>>>(ei);
    csr_scan<<<1, 1024>>>();
    csr_fill<<<(NE + 255) / 256, 256>>>(ei);

    tgemm<1,false><<<dim3(1, gy_n), 256>>>(z, in_w, in_b, p_q, NN, 64, DD);
    edge_pre<<<(NE + 7) / 8, 256>>>(pos, ei, filt_w, filt_b);

    float* mu_in = p_mu;
    float* mu_out = p_mu2;
    for (int l = 0; l < LNUM; l++) {
        tmlp<true><<<dim3(3, gy_n), 256>>>(
            p_q, iw1 + (size_t)l * DD * DD, ib1 + (size_t)l * DD,
            iw2 + (size_t)l * DD * DD3, ib2 + (size_t)l * DD3,
            (float*)p_x, NN, DD, DD3);
        if (l == 0)
            gather_msg<true><<<NN / 2, 128>>>(mu_in, mu_out);
        else
            gather_msg<false><<<NN / 2, 128>>>(mu_in, mu_out);
        tgemm<0,false><<<dim3(2, gy_3n), 256>>>(mu_out, mmw + (size_t)l * DD * 256, nullptr,
                                                p_mumix, 3 * NN, DD, 256);
        reduce_mix<<<NN, 128>>>();
        tmlp<false><<<dim3(3, gy_n), 256>>>(
            p_ctx, mw1 + (size_t)l * 256 * DD, mb1 + (size_t)l * DD,
            mw2 + (size_t)l * DD * DD3, mb2 + (size_t)l * DD3,
            p_xm, NN, 256, DD3);
        update_node<<<NN, 128>>>(mu_out);
        float* tmp = mu_in; mu_in = mu_out; mu_out = tmp;
    }

    layernorm_out<<<NN, 128>>>(lng, lnb, out);
    pos_gather<<<NN, 128>>>(mu_in, mpw, out + (size_t)NN * DD);
}

// round 15
// speedup vs baseline: 1.0495x; 1.0495x over previous
#include <cuda_runtime.h>
#include <cuda_fp16.h>
#include <math.h>

#define NN 20000
#define NE 320000
#define DD 128
#define DD3 384
#define LNUM 3

// ---------------- scratch (static device globals) ----------------
__device__ __half g_filters[(size_t)NE * DD3];  // CSR-permuted, fp16, streaming
__device__ float g_dir[(size_t)NE * 4];         // CSR-permuted
__device__ int   g_src[NE];                      // CSR-permuted source node j
__device__ int   g_slot[NE];                     // edge id -> CSR slot
__device__ float g_q[(size_t)NN * DD];
__device__ float g_h[(size_t)NN * DD];
__device__ __half g_x[(size_t)NN * DD3];        // fp16 message features
__device__ float g_mu[(size_t)NN * DD3];
__device__ float g_mu2[(size_t)NN * DD3];
__device__ float g_mumix[(size_t)NN * 768];
__device__ float g_ctx[(size_t)NN * 256];
__device__ float g_dot[(size_t)NN * DD];
__device__ float g_xm[(size_t)NN * DD3];
__device__ int g_cnt[NN];
__device__ int g_rowptr[NN + 1];

__device__ __forceinline__ float siluf(float x) { return x / (1.0f + expf(-x)); }
__device__ __forceinline__ float clip5(float x) { return fminf(fmaxf(x, -5.0f), 5.0f); }

__device__ __forceinline__ void mma_f16(float* c, const unsigned* a, const unsigned* b)
{
    asm volatile(
        "mma.sync.aligned.m16n8k16.row.col.f32.f16.f16.f32 "
        "{%0,%1,%2,%3}, {%4,%5,%6,%7}, {%8,%9}, {%0,%1,%2,%3};"
        : "+f"(c[0]), "+f"(c[1]), "+f"(c[2]), "+f"(c[3])
        : "r"(a[0]), "r"(a[1]), "r"(a[2]), "r"(a[3]), "r"(b[0]), "r"(b[1]));
}

#define HS2 140   // half2 stride: frag loads tg*4+g -> conflict-free; stores 4*140 % 32 = 16 -> conflict-free

// ---------------- FP16 tensor-core GEMM: C = act(A[M,K] @ B[K,Nc] + bias) ----------------
// BM=128, BN=128, BK=16. 256 threads = 8 warps in 2(M)x4(N); warp tile 64x32.
// fp32 global loads, fp16 smem (k-pair-packed half2), fp32 accumulate.
template<int ACT, bool OUTH>
__global__ __launch_bounds__(256) void tgemm(const float* __restrict__ A,
                                             const float* __restrict__ B,
                                             const float* __restrict__ bias,
                                             float* __restrict__ C,
                                             int M, int K, int Nc)
{
    __shared__ __half2 As2[2][8][HS2];
    __shared__ __half2 Bs2[2][8][HS2];
    int tid = threadIdx.x;
    int wid = tid >> 5, lane = tid & 31;
    int g = lane >> 2, tg = lane & 3;
    int wm = wid & 1, wn = wid >> 1;
    int row0 = blockIdx.y * 128, col0 = blockIdx.x * 128;

    int arow = tid >> 1, ak2 = (tid & 1) * 4;
    int bk2 = tid >> 5, bcol = (tid & 31) * 4;
    bool aval = (row0 + arow) < M;
    const float* Aptr = A + (size_t)(row0 + arow) * K + ak2 * 2;
    const float* Bp0 = B + (size_t)(2 * bk2) * Nc + col0 + bcol;
    const float* Bp1 = Bp0 + Nc;

    float acc[4][4][4];
#pragma unroll
    for (int mt = 0; mt < 4; mt++)
#pragma unroll
        for (int nt = 0; nt < 4; nt++)
#pragma unroll
            for (int r = 0; r < 4; r++) acc[mt][nt][r] = 0.0f;

    {
        float4 a0 = make_float4(0.f, 0.f, 0.f, 0.f), a1 = a0;
        if (aval) { a0 = *(const float4*)(Aptr); a1 = *(const float4*)(Aptr + 4); }
        As2[0][ak2 + 0][arow] = __floats2half2_rn(a0.x, a0.y);
        As2[0][ak2 + 1][arow] = __floats2half2_rn(a0.z, a0.w);
        As2[0][ak2 + 2][arow] = __floats2half2_rn(a1.x, a1.y);
        As2[0][ak2 + 3][arow] = __floats2half2_rn(a1.z, a1.w);
        float4 b0 = *(const float4*)(Bp0);
        float4 b1 = *(const float4*)(Bp1);
        Bs2[0][bk2][bcol + 0] = __floats2half2_rn(b0.x, b1.x);
        Bs2[0][bk2][bcol + 1] = __floats2half2_rn(b0.y, b1.y);
        Bs2[0][bk2][bcol + 2] = __floats2half2_rn(b0.z, b1.z);
        Bs2[0][bk2][bcol + 3] = __floats2half2_rn(b0.w, b1.w);
    }
    __syncthreads();

    int ntl = K >> 4;
    for (int t = 0; t < ntl; t++) {
        int cur = t & 1, nxt = cur ^ 1;
        float4 na0, na1, nb0, nb1;
        if (t + 1 < ntl) {
            if (aval) {
                na0 = *(const float4*)(Aptr + (t + 1) * 16);
                na1 = *(const float4*)(Aptr + (t + 1) * 16 + 4);
            } else { na0 = make_float4(0.f,0.f,0.f,0.f); na1 = na0; }
            nb0 = *(const float4*)(Bp0 + (size_t)(t + 1) * 16 * Nc);
            nb1 = *(const float4*)(Bp1 + (size_t)(t + 1) * 16 * Nc);
        }
        unsigned ar[4][4], br[4][2];
#pragma unroll
        for (int mt = 0; mt < 4; mt++) {
            int r = wm * 64 + mt * 16 + g;
            ar[mt][0] = *(const unsigned*)&As2[cur][tg][r];
            ar[mt][1] = *(const unsigned*)&As2[cur][tg][r + 8];
            ar[mt][2] = *(const unsigned*)&As2[cur][tg + 4][r];
            ar[mt][3] = *(const unsigned*)&As2[cur][tg + 4][r + 8];
        }
#pragma unroll
        for (int nt = 0; nt < 4; nt++) {
            int n0 = wn * 32 + nt * 8 + g;
            br[nt][0] = *(const unsigned*)&Bs2[cur][tg][n0];
            br[nt][1] = *(const unsigned*)&Bs2[cur][tg + 4][n0];
        }
#pragma unroll
        for (int mt = 0; mt < 4; mt++)
#pragma unroll
            for (int nt = 0; nt < 4; nt++)
                mma_f16(acc[mt][nt], ar[mt], br[nt]);

        if (t + 1 < ntl) {
            As2[nxt][ak2 + 0][arow] = __floats2half2_rn(na0.x, na0.y);
            As2[nxt][ak2 + 1][arow] = __floats2half2_rn(na0.z, na0.w);
            As2[nxt][ak2 + 2][arow] = __floats2half2_rn(na1.x, na1.y);
            As2[nxt][ak2 + 3][arow] = __floats2half2_rn(na1.z, na1.w);
            Bs2[nxt][bk2][bcol + 0] = __floats2half2_rn(nb0.x, nb1.x);
            Bs2[nxt][bk2][bcol + 1] = __floats2half2_rn(nb0.y, nb1.y);
            Bs2[nxt][bk2][bcol + 2] = __floats2half2_rn(nb0.z, nb1.z);
            Bs2[nxt][bk2][bcol + 3] = __floats2half2_rn(nb0.w, nb1.w);
        }
        __syncthreads();
    }

#pragma unroll
    for (int mt = 0; mt < 4; mt++) {
#pragma unroll
        for (int nt = 0; nt < 4; nt++) {
            int col = col0 + wn * 32 + nt * 8 + 2 * tg;
            float bb0 = 0.f, bb1 = 0.f;
            if (bias) { bb0 = bias[col]; bb1 = bias[col + 1]; }
#pragma unroll
            for (int half = 0; half < 2; half++) {
                int row = row0 + wm * 64 + mt * 16 + g + half * 8;
                if (row >= M) continue;
                float v0 = acc[mt][nt][half * 2 + 0] + bb0;
                float v1 = acc[mt][nt][half * 2 + 1] + bb1;
                if (ACT == 1) { v0 = siluf(v0); v1 = siluf(v1); }
                if (OUTH) {
                    __half2* o = (__half2*)((__half*)C + (size_t)row * Nc + col);
                    *o = __floats2half2_rn(v0, v1);
                } else {
                    *(float2*)(C + (size_t)row * Nc + col) = make_float2(v0, v1);
                }
            }
        }
    }
}

// ---------------- CSR build ----------------
__global__ void init_bufs()
{
    int idx = blockIdx.x * blockDim.x + threadIdx.x;
    if (idx < NN) g_cnt[idx] = 0;
}

__global__ void csr_count(const int* __restrict__ ei)
{
    int e = blockIdx.x * blockDim.x + threadIdx.x;
    if (e < NE) atomicAdd(&g_cnt[ei[e]], 1);
}

__global__ __launch_bounds__(1024) void csr_scan()
{
    __shared__ int part[1024];
    int t = threadIdx.x;
    const int CH = (NN + 1023) / 1024;
    int base = t * CH;
    int s = 0;
    for (int k = 0; k < CH; k++) {
        int n = base + k;
        if (n < NN) s += g_cnt[n];
    }
    part[t] = s;
    __syncthreads();
    for (int off = 1; off < 1024; off <<= 1) {
        int v = (t >= off) ? part[t - off] : 0;
        __syncthreads();
        part[t] += v;
        __syncthreads();
    }
    int run = (t == 0) ? 0 : part[t - 1];
    for (int k = 0; k < CH; k++) {
        int n = base + k;
        if (n < NN) {
            g_rowptr[n] = run;
            run += g_cnt[n];
            g_cnt[n] = 0;
        }
    }
    if (t == 1023) g_rowptr[NN] = run;
}

__global__ void csr_fill(const int* __restrict__ ei)
{
    int e = blockIdx.x * blockDim.x + threadIdx.x;
    if (e < NE) {
        int i = ei[e];
        int pos = atomicAdd(&g_cnt[i], 1);
        int slot = g_rowptr[i] + pos;
        g_slot[e] = slot;
        g_src[slot] = ei[NE + e];
    }
}

// ---------------- per-edge geometry + RBF filters (fp16, streaming stores) ----------------
__global__ __launch_bounds__(256) void edge_pre(const float* __restrict__ pos,
                                                const int* __restrict__ ei,
                                                const float* __restrict__ fw,
                                                const float* __restrict__ fb)
{
    int e = blockIdx.x * 8 + (threadIdx.x >> 5);
    if (e >= NE) return;
    int lane = threadIdx.x & 31;
    int i = ei[e], j = ei[NE + e];
    int slot = g_slot[e];
    float rx = pos[j * 3 + 0] - pos[i * 3 + 0];
    float ry = pos[j * 3 + 1] - pos[i * 3 + 1];
    float rz = pos[j * 3 + 2] - pos[i * 3 + 2];
    float d = sqrtf(rx * rx + ry * ry + rz * rz);
    d = fmaxf(d, 1e-8f);
    float dv = (lane == 0) ? rx : ((lane == 1) ? ry : rz);
    if (lane < 3) g_dir[(size_t)slot * 4 + lane] = dv / d;
    if (lane == 3) g_dir[(size_t)slot * 4 + 3] = 0.f;

    const float spacing = 5.0f / 63.0f;
    const float coeff = -0.5f / (spacing * spacing);
    float xc = fminf(d * 0.2f, 1.0f);
    float fcut = (xc < 1.0f) ? 0.5f * (cospif(xc) + 1.0f) : 0.0f;

    float4 acc0 = make_float4(0.f, 0.f, 0.f, 0.f), acc1 = acc0, acc2 = acc0;
    if (fcut > 0.0f) {
        int k0 = (int)rintf(d / spacing);
        int lo = max(0, k0 - 8), hi = min(63, k0 + 8);
        const float4* fw4 = (const float4*)fw;
        for (int k = lo; k <= hi; k++) {
            float t = d - (float)k * spacing;
            float p = expf(coeff * t * t);
            float4 w0 = fw4[k * 96 + lane];
            float4 w1 = fw4[k * 96 + lane + 32];
            float4 w2 = fw4[k * 96 + lane + 64];
            acc0.x += p * w0.x; acc0.y += p * w0.y; acc0.z += p * w0.z; acc0.w += p * w0.w;
            acc1.x += p * w1.x; acc1.y += p * w1.y; acc1.z += p * w1.z; acc1.w += p * w1.w;
            acc2.x += p * w2.x; acc2.y += p * w2.y; acc2.z += p * w2.z; acc2.w += p * w2.w;
        }
    }
    const float4* fb4 = (const float4*)fb;
    __half2* outh = (__half2*)(g_filters + (size_t)slot * DD3);
#pragma unroll
    for (int grp = 0; grp < 3; grp++) {
        float4 a = (grp == 0) ? acc0 : ((grp == 1) ? acc1 : acc2);
        float4 b = fb4[lane + 32 * grp];
        float v0 = clip5((a.x + b.x) * fcut);
        float v1 = clip5((a.y + b.y) * fcut);
        float v2 = clip5((a.z + b.z) * fcut);
        float v3 = clip5((a.w + b.w) * fcut);
        int base2 = (grp * 128 + lane * 4) >> 1;
        __stcs(outh + base2,     __floats2half2_rn(v0, v1));
        __stcs(outh + base2 + 1, __floats2half2_rn(v2, v3));
    }
}

// ---------------- CSR gather of edge messages (half2-vectorized, index-prefetch) ----------------
// 2 nodes per block; 64 threads per node; each thread owns 2 channels.
template<bool MUZERO>
__global__ __launch_bounds__(128) void gather_msg(const float* __restrict__ mu_in,
                                                  float* __restrict__ mu_out)
{
    int n = blockIdx.x * 2 + (threadIdx.x >> 6);
    int c2 = threadIdx.x & 63;
    int s = g_rowptr[n], t = g_rowptr[n + 1];
    float2 aq = make_float2(0.f, 0.f);
    float2 m0 = aq, m1 = aq, m2 = aq;
    int j_next = (s < t) ? __ldg(&g_src[s]) : 0;
    for (int k = s; k < t; k++) {
        int j = j_next;
        if (k + 1 < t) j_next = __ldg(&g_src[k + 1]);
        const __half2* f  = (const __half2*)(g_filters + (size_t)k * DD3);
        const __half2* xj = (const __half2*)(g_x + (size_t)j * DD3);
        float2 fq = __half22float2(__ldcs(f + c2));
        float2 fR = __half22float2(__ldcs(f + 64 + c2));
        float2 fm = __half22float2(__ldcs(f + 128 + c2));
        float2 xq = __half22float2(xj[c2]);
        float2 xR = __half22float2(xj[64 + c2]);
        float2 xm = __half22float2(xj[128 + c2]);
        float4 dv = __ldcs((const float4*)(g_dir + (size_t)k * 4));
        float2 dmuR = make_float2(xR.x * fR.x, xR.y * fR.y);
        aq.x += xq.x * fq.x;
        aq.y += xq.y * fq.y;
        if (MUZERO) {
            m0.x += dmuR.x * dv.x; m0.y += dmuR.y * dv.x;
            m1.x += dmuR.x * dv.y; m1.y += dmuR.y * dv.y;
            m2.x += dmuR.x * dv.z; m2.y += dmuR.y * dv.z;
        } else {
            float2 dmm = make_float2(xm.x * fm.x, xm.y * fm.y);
            const float2* muj = (const float2*)(mu_in + (size_t)j * DD3);
            float2 u0 = muj[c2], u1 = muj[64 + c2], u2 = muj[128 + c2];
            m0.x += dmuR.x * dv.x + dmm.x * u0.x; m0.y += dmuR.y * dv.x + dmm.y * u0.y;
            m1.x += dmuR.x * dv.y + dmm.x * u1.x; m1.y += dmuR.y * dv.y + dmm.y * u1.y;
            m2.x += dmuR.x * dv.z + dmm.x * u2.x; m2.y += dmuR.y * dv.z + dmm.y * u2.y;
        }
    }
    float2* qp = (float2*)(g_q + (size_t)n * DD);
    float2 qv = qp[c2];
    qv.x += aq.x; qv.y += aq.y;
    qp[c2] = qv;
    float2* muo = (float2*)(mu_out + (size_t)n * DD3);
    if (MUZERO) {
        muo[c2]       = m0;
        muo[64 + c2]  = m1;
        muo[128 + c2] = m2;
    } else {
        const float2* mui = (const float2*)(mu_in + (size_t)n * DD3);
        float2 u0 = mui[c2], u1 = mui[64 + c2], u2 = mui[128 + c2];
        u0.x += m0.x; u0.y += m0.y;
        u1.x += m1.x; u1.y += m1.y;
        u2.x += m2.x; u2.y += m2.y;
        muo[c2]       = u0;
        muo[64 + c2]  = u1;
        muo[128 + c2] = u2;
    }
}

// ---------------- mu_Vn / dot(mu_V,mu_W) / ctx ----------------
__global__ __launch_bounds__(128) void reduce_mix()
{
    int n = blockIdx.x, c = threadIdx.x;
    size_t base = (size_t)n * 768;
    float v0 = g_mumix[base + c],        w0 = g_mumix[base + 128 + c];
    float v1 = g_mumix[base + 256 + c],  w1 = g_mumix[base + 384 + c];
    float v2 = g_mumix[base + 512 + c],  w2 = g_mumix[base + 640 + c];
    float vn = sqrtf(v0 * v0 + v1 * v1 + v2 * v2 + 1e-8f);
    g_ctx[(size_t)n * 256 + c]       = g_q[(size_t)n * DD + c];
    g_ctx[(size_t)n * 256 + 128 + c] = vn;
    g_dot[(size_t)n * DD + c] = v0 * w0 + v1 * w1 + v2 * w2;
}

// ---------------- q,mu self-update ----------------
__global__ __launch_bounds__(128) void update_node(float* __restrict__ mu)
{
    int n = blockIdx.x, c = threadIdx.x;
    size_t xb = (size_t)n * DD3;
    float dq_i  = g_xm[xb + c];
    float dmu_i = g_xm[xb + DD + c];
    float dqmu  = g_xm[xb + 2 * DD + c];
    g_q[(size_t)n * DD + c] += dq_i + dqmu * g_dot[(size_t)n * DD + c];
    size_t mb = (size_t)n * 768;
#pragma unroll
    for (int a = 0; a < 3; a++)
        mu[(size_t)n * DD3 + a * DD + c] += dmu_i * g_mumix[mb + a * 256 + 128 + c];
}

// ---------------- final layernorm -> tanh ----------------
__global__ __launch_bounds__(128) void layernorm_out(const float* __restrict__ lng,
                                                     const float* __restrict__ lnb,
                                                     float* __restrict__ out)
{
    int n = blockIdx.x, c = threadIdx.x;
    float v = clip5(g_q[(size_t)n * DD + c]);
    float s = v, s2 = v * v;
#pragma unroll
    for (int o = 16; o; o >>= 1) {
        s  += __shfl_xor_sync(0xffffffffu, s, o);
        s2 += __shfl_xor_sync(0xffffffffu, s2, o);
    }
    __shared__ float sh[4], sh2[4];
    int w = c >> 5, l = c & 31;
    if (l == 0) { sh[w] = s; sh2[w] = s2; }
    __syncthreads();
    float sumv  = sh[0] + sh[1] + sh[2] + sh[3];
    float sumsq = sh2[0] + sh2[1] + sh2[2] + sh2[3];
    float mean = sumv * (1.0f / 128.0f);
    float var  = sumsq * (1.0f / 128.0f) - mean * mean;
    float y = (v - mean) * rsqrtf(var + 1e-5f) * lng[c] + lnb[c];
    out[(size_t)n * DD + c] = tanhf(y);
}

// ---------------- final mu_node gather + pos_attr (fused) ----------------
__global__ __launch_bounds__(128) void pos_gather(const float* __restrict__ mu,
                                                  const float* __restrict__ mpw,
                                                  float* __restrict__ out)
{
    int n = blockIdx.x, c = threadIdx.x;
    int s = g_rowptr[n], t = g_rowptr[n + 1];
    float s0 = 0.f, s1 = 0.f, s2v = 0.f;
    int j_next = (s < t) ? __ldg(&g_src[s]) : 0;
    for (int k = s; k < t; k++) {
        int j = j_next;
        if (k + 1 < t) j_next = __ldg(&g_src[k + 1]);
        const float* muj = mu + (size_t)j * DD3;
        s0  += muj[c];
        s1  += muj[DD + c];
        s2v += muj[2 * DD + c];
    }
    float w = mpw[c];
    s0  = clip5(s0) * w;
    s1  = clip5(s1) * w;
    s2v = clip5(s2v) * w;
#pragma unroll
    for (int o = 16; o; o >>= 1) {
        s0  += __shfl_xor_sync(0xffffffffu, s0, o);
        s1  += __shfl_xor_sync(0xffffffffu, s1, o);
        s2v += __shfl_xor_sync(0xffffffffu, s2v, o);
    }
    __shared__ float sh[4][3];
    int wd = c >> 5, l = c & 31;
    if (l == 0) { sh[wd][0] = s0; sh[wd][1] = s1; sh[wd][2] = s2v; }
    __syncthreads();
    if (c < 3) {
        float v = sh[0][c] + sh[1][c] + sh[2][c] + sh[3][c];
        out[(size_t)n * 3 + c] = clip5(v);
    }
}

// ---------------- launch ----------------
extern "C" void kernel_launch(void* const* d_in, const int* in_sizes, int n_in,
                              void* d_out, int out_size)
{
    const float* z      = (const float*)d_in[0];
    const float* pos    = (const float*)d_in[1];
    const int*   ei     = (const int*)  d_in[2];
    const float* in_w   = (const float*)d_in[3];
    const float* in_b   = (const float*)d_in[4];
    const float* filt_w = (const float*)d_in[5];
    const float* filt_b = (const float*)d_in[6];
    const float* iw1    = (const float*)d_in[7];
    const float* ib1    = (const float*)d_in[8];
    const float* iw2    = (const float*)d_in[9];
    const float* ib2    = (const float*)d_in[10];
    const float* mmw    = (const float*)d_in[11];
    const float* mw1    = (const float*)d_in[12];
    const float* mb1    = (const float*)d_in[13];
    const float* mw2    = (const float*)d_in[14];
    const float* mb2    = (const float*)d_in[15];
    const float* mpw    = (const float*)d_in[16];
    const float* lng    = (const float*)d_in[17];
    const float* lnb    = (const float*)d_in[18];
    float* out = (float*)d_out;

    float *p_q, *p_h, *p_mu, *p_mu2, *p_mumix, *p_ctx, *p_xm;
    __half* p_x;
    cudaGetSymbolAddress((void**)&p_q,     g_q);
    cudaGetSymbolAddress((void**)&p_h,     g_h);
    cudaGetSymbolAddress((void**)&p_x,     g_x);
    cudaGetSymbolAddress((void**)&p_mu,    g_mu);
    cudaGetSymbolAddress((void**)&p_mu2,   g_mu2);
    cudaGetSymbolAddress((void**)&p_mumix, g_mumix);
    cudaGetSymbolAddress((void**)&p_ctx,   g_ctx);
    cudaGetSymbolAddress((void**)&p_xm,    g_xm);

    int gy_n  = (NN + 127) / 128;        // 157
    int gy_3n = (3 * NN + 127) / 128;    // 469

    init_bufs<<<(NN + 255) / 256, 256>>>();
    csr_count<<<(NE + 255) / 256, 256>>>(ei);
    csr_scan<<<1, 1024>>>();
    csr_fill<<<(NE + 255) / 256, 256>>>(ei);

    tgemm<1,false><<<dim3(1, gy_n), 256>>>(z, in_w, in_b, p_q, NN, 64, DD);
    edge_pre<<<(NE + 7) / 8, 256>>>(pos, ei, filt_w, filt_b);

    float* mu_in = p_mu;
    float* mu_out = p_mu2;
    for (int l = 0; l < LNUM; l++) {
        tgemm<1,false><<<dim3(1, gy_n), 256>>>(p_q, iw1 + (size_t)l * DD * DD, ib1 + (size_t)l * DD,
                                               p_h, NN, DD, DD);
        tgemm<0,true><<<dim3(3, gy_n), 256>>>(p_h, iw2 + (size_t)l * DD * DD3, ib2 + (size_t)l * DD3,
                                              (float*)p_x, NN, DD, DD3);
        if (l == 0)
            gather_msg<true><<<NN / 2, 128>>>(mu_in, mu_out);
        else
            gather_msg<false><<<NN / 2, 128>>>(mu_in, mu_out);
        tgemm<0,false><<<dim3(2, gy_3n), 256>>>(mu_out, mmw + (size_t)l * DD * 256, nullptr,
                                                p_mumix, 3 * NN, DD, 256);
        reduce_mix<<<NN, 128>>>();
        tgemm<1,false><<<dim3(1, gy_n), 256>>>(p_ctx, mw1 + (size_t)l * 256 * DD, mb1 + (size_t)l * DD,
                                               p_h, NN, 256, DD);
        tgemm<0,false><<<dim3(3, gy_n), 256>>>(p_h, mw2 + (size_t)l * DD * DD3, mb2 + (size_t)l * DD3,
                                               p_xm, NN, DD, DD3);
        update_node<<<NN, 128>>>(mu_out);
        float* tmp = mu_in; mu_in = mu_out; mu_out = tmp;
    }

    layernorm_out<<<NN, 128>>>(lng, lnb, out);
    pos_gather<<<NN, 128>>>(mu_in, mpw, out + (size_t)NN * DD);
}

// round 16
// speedup vs baseline: 1.0547x; 1.0049x over previous
#include <cuda_runtime.h>
#include <cuda_fp16.h>
#include <math.h>

#define NN 20000
#define NE 320000
#define DD 128
#define DD3 384
#define LNUM 3

// ---------------- scratch (static device globals) ----------------
__device__ __half g_filters[(size_t)NE * DD3];  // CSR-permuted, fp16, streaming
__device__ float g_dir[(size_t)NE * 4];         // CSR-permuted
__device__ int   g_src[NE];                      // CSR-permuted source node j
__device__ int   g_slot[NE];                     // edge id -> CSR slot
__device__ float g_q[(size_t)NN * DD];
__device__ float g_h[(size_t)NN * DD];
__device__ __half g_x[(size_t)NN * DD3];        // fp16 message features
__device__ float g_mu[(size_t)NN * DD3];
__device__ float g_mu2[(size_t)NN * DD3];
__device__ float g_mumix[(size_t)NN * 768];
__device__ float g_ctx[(size_t)NN * 256];
__device__ float g_dot[(size_t)NN * DD];
__device__ float g_xm[(size_t)NN * DD3];
__device__ int g_cnt[NN];
__device__ int g_rowptr[NN + 1];

__device__ __forceinline__ float siluf(float x) { return x / (1.0f + expf(-x)); }
__device__ __forceinline__ float clip5(float x) { return fminf(fmaxf(x, -5.0f), 5.0f); }

__device__ __forceinline__ void mma_f16(float* c, const unsigned* a, const unsigned* b)
{
    asm volatile(
        "mma.sync.aligned.m16n8k16.row.col.f32.f16.f16.f32 "
        "{%0,%1,%2,%3}, {%4,%5,%6,%7}, {%8,%9}, {%0,%1,%2,%3};"
        : "+f"(c[0]), "+f"(c[1]), "+f"(c[2]), "+f"(c[3])
        : "r"(a[0]), "r"(a[1]), "r"(a[2]), "r"(a[3]), "r"(b[0]), "r"(b[1]));
}

#define HS2 140   // half2 stride: frag loads tg*4+g -> conflict-free; stores 4*140 % 32 = 16 -> conflict-free

// ---------------- FP16 tensor-core GEMM: C = act(A[M,K] @ B[K,Nc] + bias) ----------------
// BM=128, BN=128, BK=16. 256 threads = 8 warps in 2(M)x4(N); warp tile 64x32.
// __launch_bounds__(256,2): cap regs at 128/thread for 2 resident blocks/SM.
template<int ACT, bool OUTH>
__global__ __launch_bounds__(256, 2) void tgemm(const float* __restrict__ A,
                                                const float* __restrict__ B,
                                                const float* __restrict__ bias,
                                                float* __restrict__ C,
                                                int M, int K, int Nc)
{
    __shared__ __half2 As2[2][8][HS2];
    __shared__ __half2 Bs2[2][8][HS2];
    int tid = threadIdx.x;
    int wid = tid >> 5, lane = tid & 31;
    int g = lane >> 2, tg = lane & 3;
    int wm = wid & 1, wn = wid >> 1;
    int row0 = blockIdx.y * 128, col0 = blockIdx.x * 128;

    int arow = tid >> 1, ak2 = (tid & 1) * 4;
    int bk2 = tid >> 5, bcol = (tid & 31) * 4;
    bool aval = (row0 + arow) < M;
    const float* Aptr = A + (size_t)(row0 + arow) * K + ak2 * 2;
    const float* Bp0 = B + (size_t)(2 * bk2) * Nc + col0 + bcol;
    const float* Bp1 = Bp0 + Nc;

    float acc[4][4][4];
#pragma unroll
    for (int mt = 0; mt < 4; mt++)
#pragma unroll
        for (int nt = 0; nt < 4; nt++)
#pragma unroll
            for (int r = 0; r < 4; r++) acc[mt][nt][r] = 0.0f;

    {
        float4 a0 = make_float4(0.f, 0.f, 0.f, 0.f), a1 = a0;
        if (aval) { a0 = *(const float4*)(Aptr); a1 = *(const float4*)(Aptr + 4); }
        As2[0][ak2 + 0][arow] = __floats2half2_rn(a0.x, a0.y);
        As2[0][ak2 + 1][arow] = __floats2half2_rn(a0.z, a0.w);
        As2[0][ak2 + 2][arow] = __floats2half2_rn(a1.x, a1.y);
        As2[0][ak2 + 3][arow] = __floats2half2_rn(a1.z, a1.w);
        float4 b0 = *(const float4*)(Bp0);
        float4 b1 = *(const float4*)(Bp1);
        Bs2[0][bk2][bcol + 0] = __floats2half2_rn(b0.x, b1.x);
        Bs2[0][bk2][bcol + 1] = __floats2half2_rn(b0.y, b1.y);
        Bs2[0][bk2][bcol + 2] = __floats2half2_rn(b0.z, b1.z);
        Bs2[0][bk2][bcol + 3] = __floats2half2_rn(b0.w, b1.w);
    }
    __syncthreads();

    int ntl = K >> 4;
    for (int t = 0; t < ntl; t++) {
        int cur = t & 1, nxt = cur ^ 1;
        float4 na0, na1, nb0, nb1;
        if (t + 1 < ntl) {
            if (aval) {
                na0 = *(const float4*)(Aptr + (t + 1) * 16);
                na1 = *(const float4*)(Aptr + (t + 1) * 16 + 4);
            } else { na0 = make_float4(0.f,0.f,0.f,0.f); na1 = na0; }
            nb0 = *(const float4*)(Bp0 + (size_t)(t + 1) * 16 * Nc);
            nb1 = *(const float4*)(Bp1 + (size_t)(t + 1) * 16 * Nc);
        }
        unsigned ar[4][4], br[4][2];
#pragma unroll
        for (int mt = 0; mt < 4; mt++) {
            int r = wm * 64 + mt * 16 + g;
            ar[mt][0] = *(const unsigned*)&As2[cur][tg][r];
            ar[mt][1] = *(const unsigned*)&As2[cur][tg][r + 8];
            ar[mt][2] = *(const unsigned*)&As2[cur][tg + 4][r];
            ar[mt][3] = *(const unsigned*)&As2[cur][tg + 4][r + 8];
        }
#pragma unroll
        for (int nt = 0; nt < 4; nt++) {
            int n0 = wn * 32 + nt * 8 + g;
            br[nt][0] = *(const unsigned*)&Bs2[cur][tg][n0];
            br[nt][1] = *(const unsigned*)&Bs2[cur][tg + 4][n0];
        }
#pragma unroll
        for (int mt = 0; mt < 4; mt++)
#pragma unroll
            for (int nt = 0; nt < 4; nt++)
                mma_f16(acc[mt][nt], ar[mt], br[nt]);

        if (t + 1 < ntl) {
            As2[nxt][ak2 + 0][arow] = __floats2half2_rn(na0.x, na0.y);
            As2[nxt][ak2 + 1][arow] = __floats2half2_rn(na0.z, na0.w);
            As2[nxt][ak2 + 2][arow] = __floats2half2_rn(na1.x, na1.y);
            As2[nxt][ak2 + 3][arow] = __floats2half2_rn(na1.z, na1.w);
            Bs2[nxt][bk2][bcol + 0] = __floats2half2_rn(nb0.x, nb1.x);
            Bs2[nxt][bk2][bcol + 1] = __floats2half2_rn(nb0.y, nb1.y);
            Bs2[nxt][bk2][bcol + 2] = __floats2half2_rn(nb0.z, nb1.z);
            Bs2[nxt][bk2][bcol + 3] = __floats2half2_rn(nb0.w, nb1.w);
        }
        __syncthreads();
    }

#pragma unroll
    for (int mt = 0; mt < 4; mt++) {
#pragma unroll
        for (int nt = 0; nt < 4; nt++) {
            int col = col0 + wn * 32 + nt * 8 + 2 * tg;
            float bb0 = 0.f, bb1 = 0.f;
            if (bias) { bb0 = bias[col]; bb1 = bias[col + 1]; }
#pragma unroll
            for (int half = 0; half < 2; half++) {
                int row = row0 + wm * 64 + mt * 16 + g + half * 8;
                if (row >= M) continue;
                float v0 = acc[mt][nt][half * 2 + 0] + bb0;
                float v1 = acc[mt][nt][half * 2 + 1] + bb1;
                if (ACT == 1) { v0 = siluf(v0); v1 = siluf(v1); }
                if (OUTH) {
                    __half2* o = (__half2*)((__half*)C + (size_t)row * Nc + col);
                    *o = __floats2half2_rn(v0, v1);
                } else {
                    *(float2*)(C + (size_t)row * Nc + col) = make_float2(v0, v1);
                }
            }
        }
    }
}

// ---------------- CSR build ----------------
__global__ void init_bufs()
{
    int idx = blockIdx.x * blockDim.x + threadIdx.x;
    if (idx < NN) g_cnt[idx] = 0;
}

__global__ void csr_count(const int* __restrict__ ei)
{
    int e = blockIdx.x * blockDim.x + threadIdx.x;
    if (e < NE) atomicAdd(&g_cnt[ei[e]], 1);
}

__global__ __launch_bounds__(1024) void csr_scan()
{
    __shared__ int part[1024];
    int t = threadIdx.x;
    const int CH = (NN + 1023) / 1024;
    int base = t * CH;
    int s = 0;
    for (int k = 0; k < CH; k++) {
        int n = base + k;
        if (n < NN) s += g_cnt[n];
    }
    part[t] = s;
    __syncthreads();
    for (int off = 1; off < 1024; off <<= 1) {
        int v = (t >= off) ? part[t - off] : 0;
        __syncthreads();
        part[t] += v;
        __syncthreads();
    }
    int run = (t == 0) ? 0 : part[t - 1];
    for (int k = 0; k < CH; k++) {
        int n = base + k;
        if (n < NN) {
            g_rowptr[n] = run;
            run += g_cnt[n];
            g_cnt[n] = 0;
        }
    }
    if (t == 1023) g_rowptr[NN] = run;
}

__global__ void csr_fill(const int* __restrict__ ei)
{
    int e = blockIdx.x * blockDim.x + threadIdx.x;
    if (e < NE) {
        int i = ei[e];
        int pos = atomicAdd(&g_cnt[i], 1);
        int slot = g_rowptr[i] + pos;
        g_slot[e] = slot;
        g_src[slot] = ei[NE + e];
    }
}

// ---------------- per-edge geometry + RBF filters (fp16, streaming stores) ----------------
__global__ __launch_bounds__(256) void edge_pre(const float* __restrict__ pos,
                                                const int* __restrict__ ei,
                                                const float* __restrict__ fw,
                                                const float* __restrict__ fb)
{
    int e = blockIdx.x * 8 + (threadIdx.x >> 5);
    if (e >= NE) return;
    int lane = threadIdx.x & 31;
    int i = ei[e], j = ei[NE + e];
    int slot = g_slot[e];
    float rx = pos[j * 3 + 0] - pos[i * 3 + 0];
    float ry = pos[j * 3 + 1] - pos[i * 3 + 1];
    float rz = pos[j * 3 + 2] - pos[i * 3 + 2];
    float d = sqrtf(rx * rx + ry * ry + rz * rz);
    d = fmaxf(d, 1e-8f);
    float dv = (lane == 0) ? rx : ((lane == 1) ? ry : rz);
    if (lane < 3) g_dir[(size_t)slot * 4 + lane] = dv / d;
    if (lane == 3) g_dir[(size_t)slot * 4 + 3] = 0.f;

    const float spacing = 5.0f / 63.0f;
    const float coeff = -0.5f / (spacing * spacing);
    float xc = fminf(d * 0.2f, 1.0f);
    float fcut = (xc < 1.0f) ? 0.5f * (cospif(xc) + 1.0f) : 0.0f;

    float4 acc0 = make_float4(0.f, 0.f, 0.f, 0.f), acc1 = acc0, acc2 = acc0;
    if (fcut > 0.0f) {
        int k0 = (int)rintf(d / spacing);
        int lo = max(0, k0 - 8), hi = min(63, k0 + 8);
        const float4* fw4 = (const float4*)fw;
        for (int k = lo; k <= hi; k++) {
            float t = d - (float)k * spacing;
            float p = expf(coeff * t * t);
            float4 w0 = fw4[k * 96 + lane];
            float4 w1 = fw4[k * 96 + lane + 32];
            float4 w2 = fw4[k * 96 + lane + 64];
            acc0.x += p * w0.x; acc0.y += p * w0.y; acc0.z += p * w0.z; acc0.w += p * w0.w;
            acc1.x += p * w1.x; acc1.y += p * w1.y; acc1.z += p * w1.z; acc1.w += p * w1.w;
            acc2.x += p * w2.x; acc2.y += p * w2.y; acc2.z += p * w2.z; acc2.w += p * w2.w;
        }
    }
    const float4* fb4 = (const float4*)fb;
    __half2* outh = (__half2*)(g_filters + (size_t)slot * DD3);
#pragma unroll
    for (int grp = 0; grp < 3; grp++) {
        float4 a = (grp == 0) ? acc0 : ((grp == 1) ? acc1 : acc2);
        float4 b = fb4[lane + 32 * grp];
        float v0 = clip5((a.x + b.x) * fcut);
        float v1 = clip5((a.y + b.y) * fcut);
        float v2 = clip5((a.z + b.z) * fcut);
        float v3 = clip5((a.w + b.w) * fcut);
        int base2 = (grp * 128 + lane * 4) >> 1;
        __stcs(outh + base2,     __floats2half2_rn(v0, v1));
        __stcs(outh + base2 + 1, __floats2half2_rn(v2, v3));
    }
}

// ---------------- CSR gather of edge messages (half2-vectorized) ----------------
// 2 nodes per block; 64 threads per node; each thread owns 2 channels.
template<bool MUZERO>
__global__ __launch_bounds__(128) void gather_msg(const float* __restrict__ mu_in,
                                                  float* __restrict__ mu_out)
{
    int n = blockIdx.x * 2 + (threadIdx.x >> 6);
    int c2 = threadIdx.x & 63;
    int s = g_rowptr[n], t = g_rowptr[n + 1];
    float2 aq = make_float2(0.f, 0.f);
    float2 m0 = aq, m1 = aq, m2 = aq;
    for (int k = s; k < t; k++) {
        int j = __ldg(&g_src[k]);
        const __half2* f  = (const __half2*)(g_filters + (size_t)k * DD3);
        const __half2* xj = (const __half2*)(g_x + (size_t)j * DD3);
        float2 fq = __half22float2(__ldcs(f + c2));
        float2 fR = __half22float2(__ldcs(f + 64 + c2));
        float2 fm = __half22float2(__ldcs(f + 128 + c2));
        float2 xq = __half22float2(xj[c2]);
        float2 xR = __half22float2(xj[64 + c2]);
        float2 xm = __half22float2(xj[128 + c2]);
        float4 dv = __ldcs((const float4*)(g_dir + (size_t)k * 4));
        float2 dmuR = make_float2(xR.x * fR.x, xR.y * fR.y);
        aq.x += xq.x * fq.x;
        aq.y += xq.y * fq.y;
        if (MUZERO) {
            m0.x += dmuR.x * dv.x; m0.y += dmuR.y * dv.x;
            m1.x += dmuR.x * dv.y; m1.y += dmuR.y * dv.y;
            m2.x += dmuR.x * dv.z; m2.y += dmuR.y * dv.z;
        } else {
            float2 dmm = make_float2(xm.x * fm.x, xm.y * fm.y);
            const float2* muj = (const float2*)(mu_in + (size_t)j * DD3);
            float2 u0 = muj[c2], u1 = muj[64 + c2], u2 = muj[128 + c2];
            m0.x += dmuR.x * dv.x + dmm.x * u0.x; m0.y += dmuR.y * dv.x + dmm.y * u0.y;
            m1.x += dmuR.x * dv.y + dmm.x * u1.x; m1.y += dmuR.y * dv.y + dmm.y * u1.y;
            m2.x += dmuR.x * dv.z + dmm.x * u2.x; m2.y += dmuR.y * dv.z + dmm.y * u2.y;
        }
    }
    float2* qp = (float2*)(g_q + (size_t)n * DD);
    float2 qv = qp[c2];
    qv.x += aq.x; qv.y += aq.y;
    qp[c2] = qv;
    float2* muo = (float2*)(mu_out + (size_t)n * DD3);
    if (MUZERO) {
        muo[c2]       = m0;
        muo[64 + c2]  = m1;
        muo[128 + c2] = m2;
    } else {
        const float2* mui = (const float2*)(mu_in + (size_t)n * DD3);
        float2 u0 = mui[c2], u1 = mui[64 + c2], u2 = mui[128 + c2];
        u0.x += m0.x; u0.y += m0.y;
        u1.x += m1.x; u1.y += m1.y;
        u2.x += m2.x; u2.y += m2.y;
        muo[c2]       = u0;
        muo[64 + c2]  = u1;
        muo[128 + c2] = u2;
    }
}

// ---------------- mu_Vn / dot(mu_V,mu_W) / ctx ----------------
__global__ __launch_bounds__(128) void reduce_mix()
{
    int n = blockIdx.x, c = threadIdx.x;
    size_t base = (size_t)n * 768;
    float v0 = g_mumix[base + c],        w0 = g_mumix[base + 128 + c];
    float v1 = g_mumix[base + 256 + c],  w1 = g_mumix[base + 384 + c];
    float v2 = g_mumix[base + 512 + c],  w2 = g_mumix[base + 640 + c];
    float vn = sqrtf(v0 * v0 + v1 * v1 + v2 * v2 + 1e-8f);
    g_ctx[(size_t)n * 256 + c]       = g_q[(size_t)n * DD + c];
    g_ctx[(size_t)n * 256 + 128 + c] = vn;
    g_dot[(size_t)n * DD + c] = v0 * w0 + v1 * w1 + v2 * w2;
}

// ---------------- q,mu self-update ----------------
__global__ __launch_bounds__(128) void update_node(float* __restrict__ mu)
{
    int n = blockIdx.x, c = threadIdx.x;
    size_t xb = (size_t)n * DD3;
    float dq_i  = g_xm[xb + c];
    float dmu_i = g_xm[xb + DD + c];
    float dqmu  = g_xm[xb + 2 * DD + c];
    g_q[(size_t)n * DD + c] += dq_i + dqmu * g_dot[(size_t)n * DD + c];
    size_t mb = (size_t)n * 768;
#pragma unroll
    for (int a = 0; a < 3; a++)
        mu[(size_t)n * DD3 + a * DD + c] += dmu_i * g_mumix[mb + a * 256 + 128 + c];
}

// ---------------- final layernorm -> tanh ----------------
__global__ __launch_bounds__(128) void layernorm_out(const float* __restrict__ lng,
                                                     const float* __restrict__ lnb,
                                                     float* __restrict__ out)
{
    int n = blockIdx.x, c = threadIdx.x;
    float v = clip5(g_q[(size_t)n * DD + c]);
    float s = v, s2 = v * v;
#pragma unroll
    for (int o = 16; o; o >>= 1) {
        s  += __shfl_xor_sync(0xffffffffu, s, o);
        s2 += __shfl_xor_sync(0xffffffffu, s2, o);
    }
    __shared__ float sh[4], sh2[4];
    int w = c >> 5, l = c & 31;
    if (l == 0) { sh[w] = s; sh2[w] = s2; }
    __syncthreads();
    float sumv  = sh[0] + sh[1] + sh[2] + sh[3];
    float sumsq = sh2[0] + sh2[1] + sh2[2] + sh2[3];
    float mean = sumv * (1.0f / 128.0f);
    float var  = sumsq * (1.0f / 128.0f) - mean * mean;
    float y = (v - mean) * rsqrtf(var + 1e-5f) * lng[c] + lnb[c];
    out[(size_t)n * DD + c] = tanhf(y);
}

// ---------------- final mu_node gather + pos_attr (fused) ----------------
__global__ __launch_bounds__(128) void pos_gather(const float* __restrict__ mu,
                                                  const float* __restrict__ mpw,
                                                  float* __restrict__ out)
{
    int n = blockIdx.x, c = threadIdx.x;
    int s = g_rowptr[n], t = g_rowptr[n + 1];
    float s0 = 0.f, s1 = 0.f, s2v = 0.f;
    for (int k = s; k < t; k++) {
        int j = __ldg(&g_src[k]);
        const float* muj = mu + (size_t)j * DD3;
        s0  += muj[c];
        s1  += muj[DD + c];
        s2v += muj[2 * DD + c];
    }
    float w = mpw[c];
    s0  = clip5(s0) * w;
    s1  = clip5(s1) * w;
    s2v = clip5(s2v) * w;
#pragma unroll
    for (int o = 16; o; o >>= 1) {
        s0  += __shfl_xor_sync(0xffffffffu, s0, o);
        s1  += __shfl_xor_sync(0xffffffffu, s1, o);
        s2v += __shfl_xor_sync(0xffffffffu, s2v, o);
    }
    __shared__ float sh[4][3];
    int wd = c >> 5, l = c & 31;
    if (l == 0) { sh[wd][0] = s0; sh[wd][1] = s1; sh[wd][2] = s2v; }
    __syncthreads();
    if (c < 3) {
        float v = sh[0][c] + sh[1][c] + sh[2][c] + sh[3][c];
        out[(size_t)n * 3 + c] = clip5(v);
    }
}

// ---------------- launch ----------------
extern "C" void kernel_launch(void* const* d_in, const int* in_sizes, int n_in,
                              void* d_out, int out_size)
{
    const float* z      = (const float*)d_in[0];
    const float* pos    = (const float*)d_in[1];
    const int*   ei     = (const int*)  d_in[2];
    const float* in_w   = (const float*)d_in[3];
    const float* in_b   = (const float*)d_in[4];
    const float* filt_w = (const float*)d_in[5];
    const float* filt_b = (const float*)d_in[6];
    const float* iw1    = (const float*)d_in[7];
    const float* ib1    = (const float*)d_in[8];
    const float* iw2    = (const float*)d_in[9];
    const float* ib2    = (const float*)d_in[10];
    const float* mmw    = (const float*)d_in[11];
    const float* mw1    = (const float*)d_in[12];
    const float* mb1    = (const float*)d_in[13];
    const float* mw2    = (const float*)d_in[14];
    const float* mb2    = (const float*)d_in[15];
    const float* mpw    = (const float*)d_in[16];
    const float* lng    = (const float*)d_in[17];
    const float* lnb    = (const float*)d_in[18];
    float* out = (float*)d_out;

    float *p_q, *p_h, *p_mu, *p_mu2, *p_mumix, *p_ctx, *p_xm;
    __half* p_x;
    cudaGetSymbolAddress((void**)&p_q,     g_q);
    cudaGetSymbolAddress((void**)&p_h,     g_h);
    cudaGetSymbolAddress((void**)&p_x,     g_x);
    cudaGetSymbolAddress((void**)&p_mu,    g_mu);
    cudaGetSymbolAddress((void**)&p_mu2,   g_mu2);
    cudaGetSymbolAddress((void**)&p_mumix, g_mumix);
    cudaGetSymbolAddress((void**)&p_ctx,   g_ctx);
    cudaGetSymbolAddress((void**)&p_xm,    g_xm);

    int gy_n  = (NN + 127) / 128;        // 157
    int gy_3n = (3 * NN + 127) / 128;    // 469

    init_bufs<<<(NN + 255) / 256, 256>>>();
    csr_count<<<(NE + 255) / 256, 256>>>(ei);
    csr_scan<<<1, 1024>>>();
    csr_fill<<<(NE + 255) / 256, 256>>>(ei);

    tgemm<1,false><<<dim3(1, gy_n), 256>>>(z, in_w, in_b, p_q, NN, 64, DD);
    edge_pre<<<(NE + 7) / 8, 256>>>(pos, ei, filt_w, filt_b);

    float* mu_in = p_mu;
    float* mu_out = p_mu2;
    for (int l = 0; l < LNUM; l++) {
        tgemm<1,false><<<dim3(1, gy_n), 256>>>(p_q, iw1 + (size_t)l * DD * DD, ib1 + (size_t)l * DD,
                                               p_h, NN, DD, DD);
        tgemm<0,true><<<dim3(3, gy_n), 256>>>(p_h, iw2 + (size_t)l * DD * DD3, ib2 + (size_t)l * DD3,
                                              (float*)p_x, NN, DD, DD3);
        if (l == 0)
            gather_msg<true><<<NN / 2, 128>>>(mu_in, mu_out);
        else
            gather_msg<false><<<NN / 2, 128>>>(mu_in, mu_out);
        tgemm<0,false><<<dim3(2, gy_3n), 256>>>(mu_out, mmw + (size_t)l * DD * 256, nullptr,
                                                p_mumix, 3 * NN, DD, 256);
        reduce_mix<<<NN, 128>>>();
        tgemm<1,false><<<dim3(1, gy_n), 256>>>(p_ctx, mw1 + (size_t)l * 256 * DD, mb1 + (size_t)l * DD,
                                               p_h, NN, 256, DD);
        tgemm<0,false><<<dim3(3, gy_n), 256>>>(p_h, mw2 + (size_t)l * DD * DD3, mb2 + (size_t)l * DD3,
                                               p_xm, NN, DD, DD3);
        update_node<<<NN, 128>>>(mu_out);
        float* tmp = mu_in; mu_in = mu_out; mu_out = tmp;
    }

    layernorm_out<<<NN, 128>>>(lng, lnb, out);
    pos_gather<<<NN, 128>>>(mu_in, mpw, out + (size_t)NN * DD);
}

// round 17
// speedup vs baseline: 1.1038x; 1.0466x over previous
#include <cuda_runtime.h>
#include <cuda_fp16.h>
#include <math.h>

#define NN 20000
#define NE 320000
#define DD 128
#define DD3 384
#define LNUM 3

// ---------------- scratch (static device globals) ----------------
__device__ __half g_filters[(size_t)NE * DD3];  // CSR-permuted, fp16, streaming
__device__ float g_dir[(size_t)NE * 4];         // CSR-permuted
__device__ int   g_src[NE];                      // CSR-permuted source node j
__device__ int   g_slot[NE];                     // edge id -> CSR slot
__device__ float g_q[(size_t)NN * DD];
__device__ float g_h[(size_t)NN * DD];
__device__ __half g_x[(size_t)NN * DD3];        // fp16 message features
__device__ float g_mu[(size_t)NN * DD3];
__device__ float g_mu2[(size_t)NN * DD3];
__device__ float g_mumix[(size_t)NN * 768];
__device__ float g_ctx[(size_t)NN * 256];
__device__ float g_dot[(size_t)NN * DD];
__device__ float g_xm[(size_t)NN * DD3];
__device__ int g_cnt[NN];     // zero-initialized at load; re-zeroed at end of every launch
__device__ int g_rowptr[NN + 1];

__device__ __forceinline__ float siluf(float x) { return x / (1.0f + expf(-x)); }
__device__ __forceinline__ float clip5(float x) { return fminf(fmaxf(x, -5.0f), 5.0f); }

__device__ __forceinline__ float4 h4tof4(uint2 u)
{
    __half2 lo = *(__half2*)&u.x;
    __half2 hi = *(__half2*)&u.y;
    float2 a = __half22float2(lo);
    float2 b = __half22float2(hi);
    return make_float4(a.x, a.y, b.x, b.y);
}

__device__ __forceinline__ void mma_f16(float* c, const unsigned* a, const unsigned* b)
{
    asm volatile(
        "mma.sync.aligned.m16n8k16.row.col.f32.f16.f16.f32 "
        "{%0,%1,%2,%3}, {%4,%5,%6,%7}, {%8,%9}, {%0,%1,%2,%3};"
        : "+f"(c[0]), "+f"(c[1]), "+f"(c[2]), "+f"(c[3])
        : "r"(a[0]), "r"(a[1]), "r"(a[2]), "r"(a[3]), "r"(b[0]), "r"(b[1]));
}

#define HS2 140   // half2 stride: frag loads tg*4+g -> conflict-free; stores 4*140 % 32 = 16 -> conflict-free

// ---------------- FP16 tensor-core GEMM: C = act(A[M,K] @ B[K,Nc] + bias) ----------------
// BM=128, BN=128, BK=16. 256 threads = 8 warps in 2(M)x4(N); warp tile 64x32.
template<int ACT, bool OUTH>
__global__ __launch_bounds__(256, 2) void tgemm(const float* __restrict__ A,
                                                const float* __restrict__ B,
                                                const float* __restrict__ bias,
                                                float* __restrict__ C,
                                                int M, int K, int Nc)
{
    __shared__ __half2 As2[2][8][HS2];
    __shared__ __half2 Bs2[2][8][HS2];
    int tid = threadIdx.x;
    int wid = tid >> 5, lane = tid & 31;
    int g = lane >> 2, tg = lane & 3;
    int wm = wid & 1, wn = wid >> 1;
    int row0 = blockIdx.y * 128, col0 = blockIdx.x * 128;

    int arow = tid >> 1, ak2 = (tid & 1) * 4;
    int bk2 = tid >> 5, bcol = (tid & 31) * 4;
    bool aval = (row0 + arow) < M;
    const float* Aptr = A + (size_t)(row0 + arow) * K + ak2 * 2;
    const float* Bp0 = B + (size_t)(2 * bk2) * Nc + col0 + bcol;
    const float* Bp1 = Bp0 + Nc;

    float acc[4][4][4];
#pragma unroll
    for (int mt = 0; mt < 4; mt++)
#pragma unroll
        for (int nt = 0; nt < 4; nt++)
#pragma unroll
            for (int r = 0; r < 4; r++) acc[mt][nt][r] = 0.0f;

    {
        float4 a0 = make_float4(0.f, 0.f, 0.f, 0.f), a1 = a0;
        if (aval) { a0 = *(const float4*)(Aptr); a1 = *(const float4*)(Aptr + 4); }
        As2[0][ak2 + 0][arow] = __floats2half2_rn(a0.x, a0.y);
        As2[0][ak2 + 1][arow] = __floats2half2_rn(a0.z, a0.w);
        As2[0][ak2 + 2][arow] = __floats2half2_rn(a1.x, a1.y);
        As2[0][ak2 + 3][arow] = __floats2half2_rn(a1.z, a1.w);
        float4 b0 = *(const float4*)(Bp0);
        float4 b1 = *(const float4*)(Bp1);
        Bs2[0][bk2][bcol + 0] = __floats2half2_rn(b0.x, b1.x);
        Bs2[0][bk2][bcol + 1] = __floats2half2_rn(b0.y, b1.y);
        Bs2[0][bk2][bcol + 2] = __floats2half2_rn(b0.z, b1.z);
        Bs2[0][bk2][bcol + 3] = __floats2half2_rn(b0.w, b1.w);
    }
    __syncthreads();

    int ntl = K >> 4;
    for (int t = 0; t < ntl; t++) {
        int cur = t & 1, nxt = cur ^ 1;
        float4 na0, na1, nb0, nb1;
        if (t + 1 < ntl) {
            if (aval) {
                na0 = *(const float4*)(Aptr + (t + 1) * 16);
                na1 = *(const float4*)(Aptr + (t + 1) * 16 + 4);
            } else { na0 = make_float4(0.f,0.f,0.f,0.f); na1 = na0; }
            nb0 = *(const float4*)(Bp0 + (size_t)(t + 1) * 16 * Nc);
            nb1 = *(const float4*)(Bp1 + (size_t)(t + 1) * 16 * Nc);
        }
        unsigned ar[4][4], br[4][2];
#pragma unroll
        for (int mt = 0; mt < 4; mt++) {
            int r = wm * 64 + mt * 16 + g;
            ar[mt][0] = *(const unsigned*)&As2[cur][tg][r];
            ar[mt][1] = *(const unsigned*)&As2[cur][tg][r + 8];
            ar[mt][2] = *(const unsigned*)&As2[cur][tg + 4][r];
            ar[mt][3] = *(const unsigned*)&As2[cur][tg + 4][r + 8];
        }
#pragma unroll
        for (int nt = 0; nt < 4; nt++) {
            int n0 = wn * 32 + nt * 8 + g;
            br[nt][0] = *(const unsigned*)&Bs2[cur][tg][n0];
            br[nt][1] = *(const unsigned*)&Bs2[cur][tg + 4][n0];
        }
#pragma unroll
        for (int mt = 0; mt < 4; mt++)
#pragma unroll
            for (int nt = 0; nt < 4; nt++)
                mma_f16(acc[mt][nt], ar[mt], br[nt]);

        if (t + 1 < ntl) {
            As2[nxt][ak2 + 0][arow] = __floats2half2_rn(na0.x, na0.y);
            As2[nxt][ak2 + 1][arow] = __floats2half2_rn(na0.z, na0.w);
            As2[nxt][ak2 + 2][arow] = __floats2half2_rn(na1.x, na1.y);
            As2[nxt][ak2 + 3][arow] = __floats2half2_rn(na1.z, na1.w);
            Bs2[nxt][bk2][bcol + 0] = __floats2half2_rn(nb0.x, nb1.x);
            Bs2[nxt][bk2][bcol + 1] = __floats2half2_rn(nb0.y, nb1.y);
            Bs2[nxt][bk2][bcol + 2] = __floats2half2_rn(nb0.z, nb1.z);
            Bs2[nxt][bk2][bcol + 3] = __floats2half2_rn(nb0.w, nb1.w);
        }
        __syncthreads();
    }

#pragma unroll
    for (int mt = 0; mt < 4; mt++) {
#pragma unroll
        for (int nt = 0; nt < 4; nt++) {
            int col = col0 + wn * 32 + nt * 8 + 2 * tg;
            float bb0 = 0.f, bb1 = 0.f;
            if (bias) { bb0 = bias[col]; bb1 = bias[col + 1]; }
#pragma unroll
            for (int half = 0; half < 2; half++) {
                int row = row0 + wm * 64 + mt * 16 + g + half * 8;
                if (row >= M) continue;
                float v0 = acc[mt][nt][half * 2 + 0] + bb0;
                float v1 = acc[mt][nt][half * 2 + 1] + bb1;
                if (ACT == 1) { v0 = siluf(v0); v1 = siluf(v1); }
                if (OUTH) {
                    __half2* o = (__half2*)((__half*)C + (size_t)row * Nc + col);
                    *o = __floats2half2_rn(v0, v1);
                } else {
                    *(float2*)(C + (size_t)row * Nc + col) = make_float2(v0, v1);
                }
            }
        }
    }
}

// ---------------- CSR build ----------------
__global__ void csr_count(const int* __restrict__ ei)
{
    int e = blockIdx.x * blockDim.x + threadIdx.x;
    if (e < NE) atomicAdd(&g_cnt[ei[e]], 1);
}

__global__ __launch_bounds__(1024) void csr_scan()
{
    __shared__ int part[1024];
    int t = threadIdx.x;
    const int CH = (NN + 1023) / 1024;
    int base = t * CH;
    int s = 0;
    for (int k = 0; k < CH; k++) {
        int n = base + k;
        if (n < NN) s += g_cnt[n];
    }
    part[t] = s;
    __syncthreads();
    for (int off = 1; off < 1024; off <<= 1) {
        int v = (t >= off) ? part[t - off] : 0;
        __syncthreads();
        part[t] += v;
        __syncthreads();
    }
    int run = (t == 0) ? 0 : part[t - 1];
    for (int k = 0; k < CH; k++) {
        int n = base + k;
        if (n < NN) {
            g_rowptr[n] = run;
            run += g_cnt[n];
            g_cnt[n] = 0;
        }
    }
    if (t == 1023) g_rowptr[NN] = run;
}

__global__ void csr_fill(const int* __restrict__ ei)
{
    int e = blockIdx.x * blockDim.x + threadIdx.x;
    if (e < NE) {
        int i = ei[e];
        int pos = atomicAdd(&g_cnt[i], 1);
        int slot = g_rowptr[i] + pos;
        g_slot[e] = slot;
        g_src[slot] = ei[NE + e];
    }
}

// ---------------- per-edge geometry + RBF filters (fp16, streaming stores) ----------------
__global__ __launch_bounds__(256) void edge_pre(const float* __restrict__ pos,
                                                const int* __restrict__ ei,
                                                const float* __restrict__ fw,
                                                const float* __restrict__ fb)
{
    int e = blockIdx.x * 8 + (threadIdx.x >> 5);
    if (e >= NE) return;
    int lane = threadIdx.x & 31;
    int i = ei[e], j = ei[NE + e];
    int slot = g_slot[e];
    float rx = pos[j * 3 + 0] - pos[i * 3 + 0];
    float ry = pos[j * 3 + 1] - pos[i * 3 + 1];
    float rz = pos[j * 3 + 2] - pos[i * 3 + 2];
    float d = sqrtf(rx * rx + ry * ry + rz * rz);
    d = fmaxf(d, 1e-8f);
    float dv = (lane == 0) ? rx : ((lane == 1) ? ry : rz);
    if (lane < 3) g_dir[(size_t)slot * 4 + lane] = dv / d;
    if (lane == 3) g_dir[(size_t)slot * 4 + 3] = 0.f;

    const float spacing = 5.0f / 63.0f;
    const float coeff = -0.5f / (spacing * spacing);
    float xc = fminf(d * 0.2f, 1.0f);
    float fcut = (xc < 1.0f) ? 0.5f * (cospif(xc) + 1.0f) : 0.0f;

    float4 acc0 = make_float4(0.f, 0.f, 0.f, 0.f), acc1 = acc0, acc2 = acc0;
    if (fcut > 0.0f) {
        int k0 = (int)rintf(d / spacing);
        int lo = max(0, k0 - 8), hi = min(63, k0 + 8);
        const float4* fw4 = (const float4*)fw;
        for (int k = lo; k <= hi; k++) {
            float t = d - (float)k * spacing;
            float p = expf(coeff * t * t);
            float4 w0 = fw4[k * 96 + lane];
            float4 w1 = fw4[k * 96 + lane + 32];
            float4 w2 = fw4[k * 96 + lane + 64];
            acc0.x += p * w0.x; acc0.y += p * w0.y; acc0.z += p * w0.z; acc0.w += p * w0.w;
            acc1.x += p * w1.x; acc1.y += p * w1.y; acc1.z += p * w1.z; acc1.w += p * w1.w;
            acc2.x += p * w2.x; acc2.y += p * w2.y; acc2.z += p * w2.z; acc2.w += p * w2.w;
        }
    }
    const float4* fb4 = (const float4*)fb;
    __half2* outh = (__half2*)(g_filters + (size_t)slot * DD3);
#pragma unroll
    for (int grp = 0; grp < 3; grp++) {
        float4 a = (grp == 0) ? acc0 : ((grp == 1) ? acc1 : acc2);
        float4 b = fb4[lane + 32 * grp];
        float v0 = clip5((a.x + b.x) * fcut);
        float v1 = clip5((a.y + b.y) * fcut);
        float v2 = clip5((a.z + b.z) * fcut);
        float v3 = clip5((a.w + b.w) * fcut);
        int base2 = (grp * 128 + lane * 4) >> 1;
        __stcs(outh + base2,     __floats2half2_rn(v0, v1));
        __stcs(outh + base2 + 1, __floats2half2_rn(v2, v3));
    }
}

// ---------------- CSR gather of edge messages (1 warp/node, 4 channels/lane) ----------------
template<bool MUZERO>
__global__ __launch_bounds__(128) void gather_msg(const float* __restrict__ mu_in,
                                                  float* __restrict__ mu_out)
{
    int n = blockIdx.x * 4 + (threadIdx.x >> 5);
    int c4 = threadIdx.x & 31;           // float4 / uint2 channel group
    int s = g_rowptr[n], t = g_rowptr[n + 1];
    float4 aq = make_float4(0.f, 0.f, 0.f, 0.f);
    float4 m0 = aq, m1 = aq, m2 = aq;
    for (int k = s; k < t; k++) {
        int j = __ldg(&g_src[k]);
        const uint2* f  = (const uint2*)(g_filters + (size_t)k * DD3);
        const uint2* xj = (const uint2*)(g_x + (size_t)j * DD3);
        float4 fq = h4tof4(__ldcs(f + c4));
        float4 fR = h4tof4(__ldcs(f + 32 + c4));
        float4 fm = h4tof4(__ldcs(f + 64 + c4));
        float4 xq = h4tof4(xj[c4]);
        float4 xR = h4tof4(xj[32 + c4]);
        float4 xm = h4tof4(xj[64 + c4]);
        float4 dv = __ldcs((const float4*)(g_dir + (size_t)k * 4));
        float4 dmuR = make_float4(xR.x * fR.x, xR.y * fR.y, xR.z * fR.z, xR.w * fR.w);
        aq.x += xq.x * fq.x; aq.y += xq.y * fq.y;
        aq.z += xq.z * fq.z; aq.w += xq.w * fq.w;
        if (MUZERO) {
            m0.x += dmuR.x * dv.x; m0.y += dmuR.y * dv.x; m0.z += dmuR.z * dv.x; m0.w += dmuR.w * dv.x;
            m1.x += dmuR.x * dv.y; m1.y += dmuR.y * dv.y; m1.z += dmuR.z * dv.y; m1.w += dmuR.w * dv.y;
            m2.x += dmuR.x * dv.z; m2.y += dmuR.y * dv.z; m2.z += dmuR.z * dv.z; m2.w += dmuR.w * dv.z;
        } else {
            float4 dmm = make_float4(xm.x * fm.x, xm.y * fm.y, xm.z * fm.z, xm.w * fm.w);
            const float4* muj = (const float4*)(mu_in + (size_t)j * DD3);
            float4 u0 = muj[c4], u1 = muj[32 + c4], u2 = muj[64 + c4];
            m0.x += dmuR.x * dv.x + dmm.x * u0.x; m0.y += dmuR.y * dv.x + dmm.y * u0.y;
            m0.z += dmuR.z * dv.x + dmm.z * u0.z; m0.w += dmuR.w * dv.x + dmm.w * u0.w;
            m1.x += dmuR.x * dv.y + dmm.x * u1.x; m1.y += dmuR.y * dv.y + dmm.y * u1.y;
            m1.z += dmuR.z * dv.y + dmm.z * u1.z; m1.w += dmuR.w * dv.y + dmm.w * u1.w;
            m2.x += dmuR.x * dv.z + dmm.x * u2.x; m2.y += dmuR.y * dv.z + dmm.y * u2.y;
            m2.z += dmuR.z * dv.z + dmm.z * u2.z; m2.w += dmuR.w * dv.z + dmm.w * u2.w;
        }
    }
    float4* qp = (float4*)(g_q + (size_t)n * DD);
    float4 qv = qp[c4];
    qv.x += aq.x; qv.y += aq.y; qv.z += aq.z; qv.w += aq.w;
    qp[c4] = qv;
    float4* muo = (float4*)(mu_out + (size_t)n * DD3);
    if (MUZERO) {
        muo[c4]      = m0;
        muo[32 + c4] = m1;
        muo[64 + c4] = m2;
    } else {
        const float4* mui = (const float4*)(mu_in + (size_t)n * DD3);
        float4 u0 = mui[c4], u1 = mui[32 + c4], u2 = mui[64 + c4];
        u0.x += m0.x; u0.y += m0.y; u0.z += m0.z; u0.w += m0.w;
        u1.x += m1.x; u1.y += m1.y; u1.z += m1.z; u1.w += m1.w;
        u2.x += m2.x; u2.y += m2.y; u2.z += m2.z; u2.w += m2.w;
        muo[c4]      = u0;
        muo[32 + c4] = u1;
        muo[64 + c4] = u2;
    }
}

// ---------------- mu_Vn / dot(mu_V,mu_W) / ctx ----------------
__global__ __launch_bounds__(128) void reduce_mix()
{
    int n = blockIdx.x, c = threadIdx.x;
    size_t base = (size_t)n * 768;
    float v0 = g_mumix[base + c],        w0 = g_mumix[base + 128 + c];
    float v1 = g_mumix[base + 256 + c],  w1 = g_mumix[base + 384 + c];
    float v2 = g_mumix[base + 512 + c],  w2 = g_mumix[base + 640 + c];
    float vn = sqrtf(v0 * v0 + v1 * v1 + v2 * v2 + 1e-8f);
    g_ctx[(size_t)n * 256 + c]       = g_q[(size_t)n * DD + c];
    g_ctx[(size_t)n * 256 + 128 + c] = vn;
    g_dot[(size_t)n * DD + c] = v0 * w0 + v1 * w1 + v2 * w2;
}

// ---------------- q,mu self-update ----------------
__global__ __launch_bounds__(128) void update_node(float* __restrict__ mu)
{
    int n = blockIdx.x, c = threadIdx.x;
    size_t xb = (size_t)n * DD3;
    float dq_i  = g_xm[xb + c];
    float dmu_i = g_xm[xb + DD + c];
    float dqmu  = g_xm[xb + 2 * DD + c];
    g_q[(size_t)n * DD + c] += dq_i + dqmu * g_dot[(size_t)n * DD + c];
    size_t mb = (size_t)n * 768;
#pragma unroll
    for (int a = 0; a < 3; a++)
        mu[(size_t)n * DD3 + a * DD + c] += dmu_i * g_mumix[mb + a * 256 + 128 + c];
}

// ---------------- final layernorm -> tanh ----------------
__global__ __launch_bounds__(128) void layernorm_out(const float* __restrict__ lng,
                                                     const float* __restrict__ lnb,
                                                     float* __restrict__ out)
{
    int n = blockIdx.x, c = threadIdx.x;
    float v = clip5(g_q[(size_t)n * DD + c]);
    float s = v, s2 = v * v;
#pragma unroll
    for (int o = 16; o; o >>= 1) {
        s  += __shfl_xor_sync(0xffffffffu, s, o);
        s2 += __shfl_xor_sync(0xffffffffu, s2, o);
    }
    __shared__ float sh[4], sh2[4];
    int w = c >> 5, l = c & 31;
    if (l == 0) { sh[w] = s; sh2[w] = s2; }
    __syncthreads();
    float sumv  = sh[0] + sh[1] + sh[2] + sh[3];
    float sumsq = sh2[0] + sh2[1] + sh2[2] + sh2[3];
    float mean = sumv * (1.0f / 128.0f);
    float var  = sumsq * (1.0f / 128.0f) - mean * mean;
    float y = (v - mean) * rsqrtf(var + 1e-5f) * lng[c] + lnb[c];
    out[(size_t)n * DD + c] = tanhf(y);
}

// ---------------- final mu_node gather + pos_attr (1 warp/node) + cnt reset ----------------
__global__ __launch_bounds__(128) void pos_gather(const float* __restrict__ mu,
                                                  const float* __restrict__ mpw,
                                                  float* __restrict__ out)
{
    int n = blockIdx.x * 4 + (threadIdx.x >> 5);
    int c4 = threadIdx.x & 31;
    int s = g_rowptr[n], t = g_rowptr[n + 1];
    float4 s0 = make_float4(0.f, 0.f, 0.f, 0.f), s1 = s0, s2 = s0;
    for (int k = s; k < t; k++) {
        int j = __ldg(&g_src[k]);
        const float4* muj = (const float4*)(mu + (size_t)j * DD3);
        float4 a = muj[c4], b = muj[32 + c4], c = muj[64 + c4];
        s0.x += a.x; s0.y += a.y; s0.z += a.z; s0.w += a.w;
        s1.x += b.x; s1.y += b.y; s1.z += b.z; s1.w += b.w;
        s2.x += c.x; s2.y += c.y; s2.z += c.z; s2.w += c.w;
    }
    float4 w = ((const float4*)mpw)[c4];
    float a0 = clip5(s0.x) * w.x + clip5(s0.y) * w.y + clip5(s0.z) * w.z + clip5(s0.w) * w.w;
    float a1 = clip5(s1.x) * w.x + clip5(s1.y) * w.y + clip5(s1.z) * w.z + clip5(s1.w) * w.w;
    float a2 = clip5(s2.x) * w.x + clip5(s2.y) * w.y + clip5(s2.z) * w.z + clip5(s2.w) * w.w;
#pragma unroll
    for (int o = 16; o; o >>= 1) {
        a0 += __shfl_xor_sync(0xffffffffu, a0, o);
        a1 += __shfl_xor_sync(0xffffffffu, a1, o);
        a2 += __shfl_xor_sync(0xffffffffu, a2, o);
    }
    if (c4 == 0) {
        out[(size_t)n * 3 + 0] = clip5(a0);
        out[(size_t)n * 3 + 1] = clip5(a1);
        out[(size_t)n * 3 + 2] = clip5(a2);
        g_cnt[n] = 0;          // leave counters zeroed for the next launch (CSR rebuild)
    }
}

// ---------------- launch ----------------
extern "C" void kernel_launch(void* const* d_in, const int* in_sizes, int n_in,
                              void* d_out, int out_size)
{
    const float* z      = (const float*)d_in[0];
    const float* pos    = (const float*)d_in[1];
    const int*   ei     = (const int*)  d_in[2];
    const float* in_w   = (const float*)d_in[3];
    const float* in_b   = (const float*)d_in[4];
    const float* filt_w = (const float*)d_in[5];
    const float* filt_b = (const float*)d_in[6];
    const float* iw1    = (const float*)d_in[7];
    const float* ib1    = (const float*)d_in[8];
    const float* iw2    = (const float*)d_in[9];
    const float* ib2    = (const float*)d_in[10];
    const float* mmw    = (const float*)d_in[11];
    const float* mw1    = (const float*)d_in[12];
    const float* mb1    = (const float*)d_in[13];
    const float* mw2    = (const float*)d_in[14];
    const float* mb2    = (const float*)d_in[15];
    const float* mpw    = (const float*)d_in[16];
    const float* lng    = (const float*)d_in[17];
    const float* lnb    = (const float*)d_in[18];
    float* out = (float*)d_out;

    float *p_q, *p_h, *p_mu, *p_mu2, *p_mumix, *p_ctx, *p_xm;
    __half* p_x;
    cudaGetSymbolAddress((void**)&p_q,     g_q);
    cudaGetSymbolAddress((void**)&p_h,     g_h);
    cudaGetSymbolAddress((void**)&p_x,     g_x);
    cudaGetSymbolAddress((void**)&p_mu,    g_mu);
    cudaGetSymbolAddress((void**)&p_mu2,   g_mu2);
    cudaGetSymbolAddress((void**)&p_mumix, g_mumix);
    cudaGetSymbolAddress((void**)&p_ctx,   g_ctx);
    cudaGetSymbolAddress((void**)&p_xm,    g_xm);

    int gy_n  = (NN + 127) / 128;        // 157
    int gy_3n = (3 * NN + 127) / 128;    // 469

    csr_count<<<(NE + 255) / 256, 256>>>(ei);
    csr_scan<<<1, 1024>>>();
    csr_fill<<<(NE + 255) / 256, 256>>>(ei);

    tgemm<1,false><<<dim3(1, gy_n), 256>>>(z, in_w, in_b, p_q, NN, 64, DD);
    edge_pre<<<(NE + 7) / 8, 256>>>(pos, ei, filt_w, filt_b);

    float* mu_in = p_mu;
    float* mu_out = p_mu2;
    for (int l = 0; l < LNUM; l++) {
        tgemm<1,false><<<dim3(1, gy_n), 256>>>(p_q, iw1 + (size_t)l * DD * DD, ib1 + (size_t)l * DD,
                                               p_h, NN, DD, DD);
        tgemm<0,true><<<dim3(3, gy_n), 256>>>(p_h, iw2 + (size_t)l * DD * DD3, ib2 + (size_t)l * DD3,
                                              (float*)p_x, NN, DD, DD3);
        if (l == 0)
            gather_msg<true><<<NN / 4, 128>>>(mu_in, mu_out);
        else
            gather_msg<false><<<NN / 4, 128>>>(mu_in, mu_out);
        tgemm<0,false><<<dim3(2, gy_3n), 256>>>(mu_out, mmw + (size_t)l * DD * 256, nullptr,
                                                p_mumix, 3 * NN, DD, 256);
        reduce_mix<<<NN, 128>>>();
        tgemm<1,false><<<dim3(1, gy_n), 256>>>(p_ctx, mw1 + (size_t)l * 256 * DD, mb1 + (size_t)l * DD,
                                               p_h, NN, 256, DD);
        tgemm<0,false><<<dim3(3, gy_n), 256>>>(p_h, mw2 + (size_t)l * DD * DD3, mb2 + (size_t)l * DD3,
                                               p_xm, NN, DD, DD3);
        update_node<<<NN, 128>>>(mu_out);
        float* tmp = mu_in; mu_in = mu_out; mu_out = tmp;
    }

    layernorm_out<<<NN, 128>>>(lng, lnb, out);
    pos_gather<<<NN / 4, 128>>>(mu_in, mpw, out + (size_t)NN * DD);
}